// round 12
// baseline (speedup 1.0000x reference)
#include <cuda_runtime.h>
#include <cuda_bf16.h>
#include <cstdint>

#define B_ 2
#define L_ 2048
#define D_ 768
#define H_ 12
#define DH_ 64
#define M_ (B_*L_)
#define DFF_ 2304
#define UPN_ (2*DFF_)

// ---------------- scratch ----------------
__device__ float g_x1 [M_*D_];
__device__ float g_x2 [M_*D_];

__device__ __nv_bfloat16 g_norm_bf [M_*D_];
__device__ __nv_bfloat16 g_normc_bf[M_*D_];
__device__ __nv_bfloat16 g_qkv_bf  [M_*2304];
__device__ __nv_bfloat16 g_lin2_bf [M_*D_];
__device__ __nv_bfloat16 g_q_bf    [B_*H_*L_*DH_];
__device__ __nv_bfloat16 g_k_bf    [B_*H_*L_*DH_];
__device__ __nv_bfloat16 g_v_bf    [B_*H_*L_*DH_];
__device__ __nv_bfloat16 g_ao_bf   [M_*D_];
__device__ __nv_bfloat16 g_ag_bf   [M_*DFF_];

__device__ __nv_bfloat16 g_wqkv_bf [2304*768];
__device__ __nv_bfloat16 g_wout1_bf[768*768];
__device__ __nv_bfloat16 g_wq_bf   [768*768];
__device__ __nv_bfloat16 g_wkv_bf  [1536*768];
__device__ __nv_bfloat16 g_wout2_bf[768*768];
__device__ __nv_bfloat16 g_wup_bf  [4608*768];   // permuted: row 2j=a_j, 2j+1=g_j
__device__ __nv_bfloat16 g_wdown_bf[768*2304];

// ---------------- mma / ldmatrix helpers ----------------
__device__ __forceinline__ void mma_bf16(float c[4], const uint32_t a[4], const uint32_t b[2]) {
    asm volatile("mma.sync.aligned.m16n8k16.row.col.f32.bf16.bf16.f32 "
                 "{%0,%1,%2,%3},{%4,%5,%6,%7},{%8,%9},{%0,%1,%2,%3};\n"
                 : "+f"(c[0]), "+f"(c[1]), "+f"(c[2]), "+f"(c[3])
                 : "r"(a[0]), "r"(a[1]), "r"(a[2]), "r"(a[3]), "r"(b[0]), "r"(b[1]));
}
__device__ __forceinline__ void ldsm_x4(uint32_t r[4], uint32_t addr) {
    asm volatile("ldmatrix.sync.aligned.m8n8.x4.shared.b16 {%0,%1,%2,%3}, [%4];"
                 : "=r"(r[0]), "=r"(r[1]), "=r"(r[2]), "=r"(r[3]) : "r"(addr));
}
__device__ __forceinline__ void ldsm_x4_t(uint32_t r[4], uint32_t addr) {
    asm volatile("ldmatrix.sync.aligned.m8n8.x4.trans.shared.b16 {%0,%1,%2,%3}, [%4];"
                 : "=r"(r[0]), "=r"(r[1]), "=r"(r[2]), "=r"(r[3]) : "r"(addr));
}
__device__ __forceinline__ uint32_t pk_bf(float a, float b) {
    __nv_bfloat162 t = __floats2bfloat162_rn(a, b);
    return *(uint32_t*)&t;
}

// ---------------- fused weight conversion ----------------
struct ConvTab {
    const float4* src[6];
    uint2*        dst[6];
    int           n4[6];
};
__global__ void conv6_kernel(ConvTab t) {
    int r = blockIdx.y;
    int i = blockIdx.x * 256 + threadIdx.x;
    if (i >= t.n4[r]) return;
    float4 v = t.src[r][i];
    __nv_bfloat162 lo = __floats2bfloat162_rn(v.x, v.y);
    __nv_bfloat162 hi = __floats2bfloat162_rn(v.z, v.w);
    uint2 o; o.x = *(uint32_t*)&lo; o.y = *(uint32_t*)&hi;
    t.dst[r][i] = o;
}
__global__ void convup_kernel(const float* __restrict__ src, __nv_bfloat16* __restrict__ dst) {
    int i = blockIdx.x * 256 + threadIdx.x;
    if (i >= UPN_ * (D_ / 4)) return;
    int p  = i / (D_ / 4);
    int kc = (i % (D_ / 4)) * 4;
    int srow = (p & 1) ? (DFF_ + (p >> 1)) : (p >> 1);
    float4 v = *(const float4*)(src + (size_t)srow * D_ + kc);
    __nv_bfloat162 lo = __floats2bfloat162_rn(v.x, v.y);
    __nv_bfloat162 hi = __floats2bfloat162_rn(v.z, v.w);
    uint2 o; o.x = *(uint32_t*)&lo; o.y = *(uint32_t*)&hi;
    *(uint2*)(dst + (size_t)p * D_ + kc) = o;
}

// ---------------- rmsnorm -> bf16 (dual-source variant via grid.y) ----------
__device__ __forceinline__ void rms_row(const float* xr, const float* sc,
                                        __nv_bfloat16* outr) {
    float s = 0.f;
    for (int i = threadIdx.x; i < D_; i += 256) { float v = xr[i]; s += v * v; }
    #pragma unroll
    for (int o = 16; o > 0; o >>= 1) s += __shfl_xor_sync(0xffffffffu, s, o);
    __shared__ float red[8];
    __shared__ float rtot;
    if ((threadIdx.x & 31) == 0) red[threadIdx.x >> 5] = s;
    __syncthreads();
    if (threadIdx.x == 0) {
        float t = 0.f;
        #pragma unroll
        for (int i = 0; i < 8; i++) t += red[i];
        rtot = rsqrtf(t / (float)D_ + 1e-6f);
    }
    __syncthreads();
    float r = rtot;
    for (int i = threadIdx.x; i < D_; i += 256)
        outr[i] = __float2bfloat16(xr[i] * sc[i] * r);
}
__global__ void rmsnorm_kernel(const float* __restrict__ x, const float* __restrict__ sc,
                               __nv_bfloat16* __restrict__ out) {
    int row = blockIdx.x;
    rms_row(x + (size_t)row * D_, sc, out + (size_t)row * D_);
}
__global__ void rmsnorm2_kernel(const float* __restrict__ xa, const float* __restrict__ sa,
                                __nv_bfloat16* __restrict__ oa,
                                const float* __restrict__ xb, const float* __restrict__ sb,
                                __nv_bfloat16* __restrict__ ob) {
    int row = blockIdx.x;
    if (blockIdx.y == 0) rms_row(xa + (size_t)row * D_, sa, oa + (size_t)row * D_);
    else                 rms_row(xb + (size_t)row * D_, sb, ob + (size_t)row * D_);
}

// ---------------- bf16 GEMM NT (narrow): BM x 128, BK=64, 3-stage ----------
#define SLDH 72
#define GSMEM(BM) (3 * ((BM) + 128) * SLDH * 2)

template<int BM, int MODE>
__global__ __launch_bounds__(256, 2)
void gemm_bf16(const __nv_bfloat16* __restrict__ A,
               const __nv_bfloat16* __restrict__ Bw,
               const float* __restrict__ R,
               float* __restrict__ Cf,
               __nv_bfloat16* __restrict__ Cb,
               int M, int N, int K) {
    extern __shared__ __nv_bfloat16 smh[];
    constexpr int ATILE = BM * SLDH;
    constexpr int BTILE = 128 * SLDH;
    constexpr int MI = BM / 32;
    __nv_bfloat16* As = smh;
    __nv_bfloat16* Bs = smh + 3 * ATILE;

    const int tid = threadIdx.x;
    const int m0 = blockIdx.y * BM, n0 = blockIdx.x * 128;
    const int w = tid >> 5, lane = tid & 31;
    const int wm = w >> 2, wn = w & 3;
    const int g = lane >> 2, t4 = lane & 3;

    const int arow = (lane & 7) + ((lane >> 3) & 1) * 8;
    const int acol = (lane >> 4) * 8;
    const int brow = (lane & 7) + (lane >> 4) * 8;
    const int bcol = ((lane >> 3) & 1) * 8;

    float acc[MI][4][4];
    #pragma unroll
    for (int i = 0; i < MI; i++)
        #pragma unroll
        for (int j = 0; j < 4; j++)
            #pragma unroll
            for (int r = 0; r < 4; r++) acc[i][j][r] = 0.f;

    auto load_tiles = [&](int stage, int k0) {
        __nv_bfloat16* as = As + stage * ATILE;
        __nv_bfloat16* bs = Bs + stage * BTILE;
        #pragma unroll
        for (int i = 0; i < BM / 32; i++) {
            int id = tid + i * 256;
            int r = id >> 3, c = (id & 7) * 8;
            uint32_t sa = (uint32_t)__cvta_generic_to_shared(as + r * SLDH + c);
            const __nv_bfloat16* ga = A + (size_t)(m0 + r) * K + k0 + c;
            asm volatile("cp.async.cg.shared.global [%0], [%1], 16;\n" :: "r"(sa), "l"(ga));
        }
        #pragma unroll
        for (int i = 0; i < 4; i++) {
            int id = tid + i * 256;
            int r = id >> 3, c = (id & 7) * 8;
            uint32_t sb = (uint32_t)__cvta_generic_to_shared(bs + r * SLDH + c);
            const __nv_bfloat16* gb = Bw + (size_t)(n0 + r) * K + k0 + c;
            asm volatile("cp.async.cg.shared.global [%0], [%1], 16;\n" :: "r"(sb), "l"(gb));
        }
        asm volatile("cp.async.commit_group;\n");
    };

    const int numK = K >> 6;
    load_tiles(0, 0);
    load_tiles(1, 64);

    for (int kt = 0; kt < numK; kt++) {
        if (kt + 1 < numK) asm volatile("cp.async.wait_group 1;\n");
        else               asm volatile("cp.async.wait_group 0;\n");
        __syncthreads();
        if (kt + 2 < numK) load_tiles((kt + 2) % 3, (kt + 2) * 64);

        const __nv_bfloat16* as = As + (kt % 3) * ATILE;
        const __nv_bfloat16* bs = Bs + (kt % 3) * BTILE;

        #pragma unroll
        for (int kb = 0; kb < 4; kb++) {
            uint32_t af[MI][4], bf[4][2];
            #pragma unroll
            for (int mi = 0; mi < MI; mi++) {
                int mr = wm * (BM / 2) + mi * 16 + arow;
                uint32_t ad = (uint32_t)__cvta_generic_to_shared(as + mr * SLDH + kb * 16 + acol);
                ldsm_x4(af[mi], ad);
            }
            #pragma unroll
            for (int np = 0; np < 2; np++) {
                int nr = wn * 32 + np * 16 + brow;
                uint32_t bd = (uint32_t)__cvta_generic_to_shared(bs + nr * SLDH + kb * 16 + bcol);
                uint32_t q[4];
                ldsm_x4(q, bd);
                bf[np*2  ][0] = q[0]; bf[np*2  ][1] = q[1];
                bf[np*2+1][0] = q[2]; bf[np*2+1][1] = q[3];
            }
            #pragma unroll
            for (int mi = 0; mi < MI; mi++)
                #pragma unroll
                for (int ni = 0; ni < 4; ni++)
                    mma_bf16(acc[mi][ni], af[mi], bf[ni]);
        }
    }

    #pragma unroll
    for (int mi = 0; mi < MI; mi++) {
        int r0 = m0 + wm * (BM / 2) + mi * 16 + g;
        #pragma unroll
        for (int ni = 0; ni < 4; ni++) {
            int cc = n0 + wn * 32 + ni * 8 + 2 * t4;
            float a0 = acc[mi][ni][0], a1 = acc[mi][ni][1];
            float a2 = acc[mi][ni][2], a3 = acc[mi][ni][3];
            if (MODE == 0) {
                float2 r0v = *(const float2*)(R + (size_t)r0 * N + cc);
                float2 r1v = *(const float2*)(R + (size_t)(r0 + 8) * N + cc);
                *(float2*)(Cf + (size_t)r0 * N + cc)       = make_float2(a0 + r0v.x, a1 + r0v.y);
                *(float2*)(Cf + (size_t)(r0 + 8) * N + cc) = make_float2(a2 + r1v.x, a3 + r1v.y);
            } else if (MODE == 1) {
                *(__nv_bfloat162*)(Cb + (size_t)r0 * N + cc)       = __floats2bfloat162_rn(a0, a1);
                *(__nv_bfloat162*)(Cb + (size_t)(r0 + 8) * N + cc) = __floats2bfloat162_rn(a2, a3);
            } else {
                int jj = cc >> 1;
                float s0 = a0 * (a1 / (1.f + __expf(-a1)));
                float s1 = a2 * (a3 / (1.f + __expf(-a3)));
                Cb[(size_t)r0 * DFF_ + jj]       = __float2bfloat16(s0);
                Cb[(size_t)(r0 + 8) * DFF_ + jj] = __float2bfloat16(s1);
            }
        }
    }
}

// ---------------- bf16 GEMM NT (wide): 128x256 CTA, warp tile 64x64 ---------
// 8 warps (2x4), BK=64, 3-stage, 1 CTA/SM (regs ~190). MODE 1 / 2 only.
#define WGSMEM (3 * (128 + 256) * SLDH * 2)   // 165888 bytes

template<int MODE>
__global__ __launch_bounds__(256, 1)
void gemm_wide(const __nv_bfloat16* __restrict__ A,
               const __nv_bfloat16* __restrict__ Bw,
               __nv_bfloat16* __restrict__ Cb,
               int M, int N, int K) {
    extern __shared__ __nv_bfloat16 smh[];
    constexpr int ATILE = 128 * SLDH;
    constexpr int BTILE = 256 * SLDH;
    __nv_bfloat16* As = smh;
    __nv_bfloat16* Bs = smh + 3 * ATILE;

    const int tid = threadIdx.x;
    const int m0 = blockIdx.y * 128, n0 = blockIdx.x * 256;
    const int w = tid >> 5, lane = tid & 31;
    const int wm = w >> 2, wn = w & 3;
    const int g = lane >> 2, t4 = lane & 3;

    const int arow = (lane & 7) + ((lane >> 3) & 1) * 8;
    const int acol = (lane >> 4) * 8;
    const int brow = (lane & 7) + (lane >> 4) * 8;
    const int bcol = ((lane >> 3) & 1) * 8;

    float acc[4][8][4];
    #pragma unroll
    for (int i = 0; i < 4; i++)
        #pragma unroll
        for (int j = 0; j < 8; j++)
            #pragma unroll
            for (int r = 0; r < 4; r++) acc[i][j][r] = 0.f;

    auto load_tiles = [&](int stage, int k0) {
        __nv_bfloat16* as = As + stage * ATILE;
        __nv_bfloat16* bs = Bs + stage * BTILE;
        #pragma unroll
        for (int i = 0; i < 4; i++) {
            int id = tid + i * 256;
            int r = id >> 3, c = (id & 7) * 8;
            uint32_t sa = (uint32_t)__cvta_generic_to_shared(as + r * SLDH + c);
            const __nv_bfloat16* ga = A + (size_t)(m0 + r) * K + k0 + c;
            asm volatile("cp.async.cg.shared.global [%0], [%1], 16;\n" :: "r"(sa), "l"(ga));
        }
        #pragma unroll
        for (int i = 0; i < 8; i++) {
            int id = tid + i * 256;
            int r = id >> 3, c = (id & 7) * 8;
            uint32_t sb = (uint32_t)__cvta_generic_to_shared(bs + r * SLDH + c);
            const __nv_bfloat16* gb = Bw + (size_t)(n0 + r) * K + k0 + c;
            asm volatile("cp.async.cg.shared.global [%0], [%1], 16;\n" :: "r"(sb), "l"(gb));
        }
        asm volatile("cp.async.commit_group;\n");
    };

    const int numK = K >> 6;
    load_tiles(0, 0);
    load_tiles(1, 64);

    for (int kt = 0; kt < numK; kt++) {
        if (kt + 1 < numK) asm volatile("cp.async.wait_group 1;\n");
        else               asm volatile("cp.async.wait_group 0;\n");
        __syncthreads();
        if (kt + 2 < numK) load_tiles((kt + 2) % 3, (kt + 2) * 64);

        const __nv_bfloat16* as = As + (kt % 3) * ATILE;
        const __nv_bfloat16* bs = Bs + (kt % 3) * BTILE;

        #pragma unroll
        for (int kb = 0; kb < 4; kb++) {
            uint32_t af[4][4], bf[8][2];
            #pragma unroll
            for (int mi = 0; mi < 4; mi++) {
                int mr = wm * 64 + mi * 16 + arow;
                uint32_t ad = (uint32_t)__cvta_generic_to_shared(as + mr * SLDH + kb * 16 + acol);
                ldsm_x4(af[mi], ad);
            }
            #pragma unroll
            for (int np = 0; np < 4; np++) {
                int nr = wn * 64 + np * 16 + brow;
                uint32_t bd = (uint32_t)__cvta_generic_to_shared(bs + nr * SLDH + kb * 16 + bcol);
                uint32_t q[4];
                ldsm_x4(q, bd);
                bf[np*2  ][0] = q[0]; bf[np*2  ][1] = q[1];
                bf[np*2+1][0] = q[2]; bf[np*2+1][1] = q[3];
            }
            #pragma unroll
            for (int mi = 0; mi < 4; mi++)
                #pragma unroll
                for (int ni = 0; ni < 8; ni++)
                    mma_bf16(acc[mi][ni], af[mi], bf[ni]);
        }
    }

    #pragma unroll
    for (int mi = 0; mi < 4; mi++) {
        int r0 = m0 + wm * 64 + mi * 16 + g;
        #pragma unroll
        for (int ni = 0; ni < 8; ni++) {
            int cc = n0 + wn * 64 + ni * 8 + 2 * t4;
            float a0 = acc[mi][ni][0], a1 = acc[mi][ni][1];
            float a2 = acc[mi][ni][2], a3 = acc[mi][ni][3];
            if (MODE == 1) {
                *(__nv_bfloat162*)(Cb + (size_t)r0 * N + cc)       = __floats2bfloat162_rn(a0, a1);
                *(__nv_bfloat162*)(Cb + (size_t)(r0 + 8) * N + cc) = __floats2bfloat162_rn(a2, a3);
            } else {
                int jj = cc >> 1;
                float s0 = a0 * (a1 / (1.f + __expf(-a1)));
                float s1 = a2 * (a3 / (1.f + __expf(-a3)));
                Cb[(size_t)r0 * DFF_ + jj]       = __float2bfloat16(s0);
                Cb[(size_t)(r0 + 8) * DFF_ + jj] = __float2bfloat16(s1);
            }
        }
    }
}

// ---------------- fused q/k cos-scale+RoPE + v copy (2 warps per item) ------
__device__ __forceinline__ float theta_of(int j, int h, float p0, float p1, float p2) {
    int i = j >> 3, f = j & 7;
    float pc = (i == 0) ? p0 : ((i == 1) ? p1 : p2);
    float freq = 3.14159265358979f * __expf((float)(f * 12 + h) * 0.02398526136f);
    return pc * freq;
}

__device__ __forceinline__ void rope_vec(float* shrow, float v0, float v1,
                                         int lane, int h, float sscale,
                                         float p0, float p1, float p2,
                                         __nv_bfloat16* dst) {
    float ss = v0 * v0 + v1 * v1;
    #pragma unroll
    for (int o = 16; o > 0; o >>= 1) ss += __shfl_xor_sync(0xffffffffu, ss, o);
    float f = sscale * rsqrtf(ss + 1e-6f);
    shrow[lane] = v0 * f; shrow[lane + 32] = v1 * f;
    __syncwarp();

    float out0, out1;
    {
        int d = lane;
        if (d < 24) {
            float th = theta_of(d, h, p0, p1, p2);
            float s, c; __sincosf(th, &s, &c);
            out0 = shrow[d] * c - shrow[d + 24] * s;
        } else {
            float th = theta_of(d - 24, h, p0, p1, p2);
            float s, c; __sincosf(th, &s, &c);
            out0 = shrow[d] * c + shrow[d - 24] * s;
        }
    }
    {
        int d = lane + 32;
        if (d < 48) {
            float th = theta_of(d - 24, h, p0, p1, p2);
            float s, c; __sincosf(th, &s, &c);
            out1 = shrow[d] * c + shrow[d - 24] * s;
        } else {
            out1 = shrow[d];
        }
    }
    __syncwarp();
    dst[lane] = __float2bfloat16(out0);
    dst[lane + 32] = __float2bfloat16(out1);
}

__global__ void qkv_pack(const __nv_bfloat16* __restrict__ srcq, int strq, int offq,
                         const __nv_bfloat16* __restrict__ srck, int strk, int offk, int offv,
                         const float* __restrict__ posq, const float* __restrict__ posk,
                         const float* __restrict__ hscale,
                         __nv_bfloat16* __restrict__ dq, __nv_bfloat16* __restrict__ dk,
                         __nv_bfloat16* __restrict__ dv) {
    int gw = (blockIdx.x * blockDim.x + threadIdx.x) >> 5;
    int lane = threadIdx.x & 31;
    int item = gw >> 1, role = gw & 1;
    if (item >= B_ * L_ * H_) return;
    int h = item % H_;
    int bl = item / H_;
    int b = bl / L_, l = bl % L_;

    __shared__ float sh[8][64];
    float* shrow = sh[threadIdx.x >> 5];
    size_t hdst = ((size_t)(b * H_ + h) * L_ + l) * DH_;
    float s = sqrtf(hscale[h]);

    if (role == 0) {
        const __nv_bfloat16* sp = srcq + (size_t)bl * strq + offq + h * DH_;
        float v0 = __bfloat162float(sp[lane]), v1 = __bfloat162float(sp[lane + 32]);
        float p0 = posq[(size_t)bl * 3 + 0], p1 = posq[(size_t)bl * 3 + 1], p2 = posq[(size_t)bl * 3 + 2];
        rope_vec(shrow, v0, v1, lane, h, s, p0, p1, p2, dq + hdst);
    } else {
        const __nv_bfloat16* sp = srck + (size_t)bl * strk + offk + h * DH_;
        float v0 = __bfloat162float(sp[lane]), v1 = __bfloat162float(sp[lane + 32]);
        float p0 = posk[(size_t)bl * 3 + 0], p1 = posk[(size_t)bl * 3 + 1], p2 = posk[(size_t)bl * 3 + 2];
        rope_vec(shrow, v0, v1, lane, h, s, p0, p1, p2, dk + hdst);
        if (lane < 8) {
            *(uint4*)(dv + hdst + lane * 8) =
                *(const uint4*)(srck + (size_t)bl * strk + offv + h * DH_ + lane * 8);
        }
    }
}

// ---------------- bf16 flash attention, 3-stage cp.async KV pipeline ---------
#define ALD 72
#define ATT_STAGE (128 * ALD)
#define ATT_SMEM (3 * ATT_STAGE * 2)

__global__ __launch_bounds__(256, 2) void attn_bf(const __nv_bfloat16* __restrict__ Q,
                                                  const __nv_bfloat16* __restrict__ K,
                                                  const __nv_bfloat16* __restrict__ V,
                                                  __nv_bfloat16* __restrict__ O) {
    extern __shared__ __nv_bfloat16 KVs[];

    const int bh = blockIdx.y;
    const int q0 = blockIdx.x * 128;
    const int tid = threadIdx.x;
    const int w = tid >> 5, lane = tid & 31;
    const int g = lane >> 2, t4 = lane & 3;

    const int arow = (lane & 7) + ((lane >> 3) & 1) * 8;
    const int acol = (lane >> 4) * 8;
    const int brow = (lane & 7) + (lane >> 4) * 8;
    const int bcol = ((lane >> 3) & 1) * 8;
    const int vrow = (lane & 7) + ((lane >> 3) & 1) * 8;
    const int vcol = (lane >> 4) * 8;

    const __nv_bfloat16* qb = Q + ((size_t)bh * L_ + q0) * DH_;
    #pragma unroll
    for (int i = 0; i < 4; i++) {
        int idx = tid + i * 256;
        int r = idx >> 3, c = (idx & 7) * 8;
        *(uint4*)(KVs + r * ALD + c) = *(const uint4*)(qb + r * 64 + c);
    }
    __syncthreads();
    uint32_t qf[4][4];
    #pragma unroll
    for (int kb = 0; kb < 4; kb++) {
        uint32_t ad = (uint32_t)__cvta_generic_to_shared(
            KVs + (w * 16 + arow) * ALD + kb * 16 + acol);
        ldsm_x4(qf[kb], ad);
    }
    __syncthreads();

    const __nv_bfloat16* kbase = K + (size_t)bh * L_ * DH_;
    const __nv_bfloat16* vbase = V + (size_t)bh * L_ * DH_;

    auto load_kv = [&](int stage, int kt) {
        __nv_bfloat16* Ks = KVs + stage * ATT_STAGE;
        __nv_bfloat16* Vs = Ks + 64 * ALD;
        #pragma unroll
        for (int i = 0; i < 2; i++) {
            int idx = tid + i * 256;
            int r = idx >> 3, c = (idx & 7) * 8;
            uint32_t sk = (uint32_t)__cvta_generic_to_shared(Ks + r * ALD + c);
            asm volatile("cp.async.cg.shared.global [%0], [%1], 16;\n"
                         :: "r"(sk), "l"(kbase + (size_t)(kt + r) * 64 + c));
            uint32_t sv = (uint32_t)__cvta_generic_to_shared(Vs + r * ALD + c);
            asm volatile("cp.async.cg.shared.global [%0], [%1], 16;\n"
                         :: "r"(sv), "l"(vbase + (size_t)(kt + r) * 64 + c));
        }
        asm volatile("cp.async.commit_group;\n");
    };

    float ob[8][4];
    #pragma unroll
    for (int n = 0; n < 8; n++)
        #pragma unroll
        for (int r = 0; r < 4; r++) ob[n][r] = 0.f;
    float m0 = -1e30f, m1 = -1e30f, l0 = 0.f, l1 = 0.f;

    const int nt = L_ / 64;
    load_kv(0, 0);
    load_kv(1, 64);

    for (int t = 0; t < nt; t++) {
        if (t + 1 < nt) asm volatile("cp.async.wait_group 1;\n");
        else            asm volatile("cp.async.wait_group 0;\n");
        __syncthreads();
        if (t + 2 < nt) load_kv((t + 2) % 3, (t + 2) * 64);

        const __nv_bfloat16* Ks = KVs + (t % 3) * ATT_STAGE;
        const __nv_bfloat16* Vs = Ks + 64 * ALD;

        float sc[8][4];
        #pragma unroll
        for (int n = 0; n < 8; n++)
            #pragma unroll
            for (int r = 0; r < 4; r++) sc[n][r] = 0.f;
        #pragma unroll
        for (int kb = 0; kb < 4; kb++) {
            uint32_t bf[8][2];
            #pragma unroll
            for (int np = 0; np < 4; np++) {
                uint32_t bd = (uint32_t)__cvta_generic_to_shared(
                    Ks + (np * 16 + brow) * ALD + kb * 16 + bcol);
                uint32_t q[4];
                ldsm_x4(q, bd);
                bf[np*2  ][0] = q[0]; bf[np*2  ][1] = q[1];
                bf[np*2+1][0] = q[2]; bf[np*2+1][1] = q[3];
            }
            #pragma unroll
            for (int n = 0; n < 8; n++)
                mma_bf16(sc[n], qf[kb], bf[n]);
        }

        float rm0 = -1e30f, rm1 = -1e30f;
        #pragma unroll
        for (int n = 0; n < 8; n++) {
            rm0 = fmaxf(rm0, fmaxf(sc[n][0], sc[n][1]));
            rm1 = fmaxf(rm1, fmaxf(sc[n][2], sc[n][3]));
        }
        rm0 = fmaxf(rm0, __shfl_xor_sync(0xffffffffu, rm0, 1));
        rm0 = fmaxf(rm0, __shfl_xor_sync(0xffffffffu, rm0, 2));
        rm1 = fmaxf(rm1, __shfl_xor_sync(0xffffffffu, rm1, 1));
        rm1 = fmaxf(rm1, __shfl_xor_sync(0xffffffffu, rm1, 2));
        float nm0 = fmaxf(m0, rm0), nm1 = fmaxf(m1, rm1);
        float c0 = __expf(m0 - nm0), c1 = __expf(m1 - nm1);
        m0 = nm0; m1 = nm1;

        float ps0 = 0.f, ps1 = 0.f;
        #pragma unroll
        for (int n = 0; n < 8; n++) {
            sc[n][0] = __expf(sc[n][0] - nm0);
            sc[n][1] = __expf(sc[n][1] - nm0);
            sc[n][2] = __expf(sc[n][2] - nm1);
            sc[n][3] = __expf(sc[n][3] - nm1);
            ps0 += sc[n][0] + sc[n][1];
            ps1 += sc[n][2] + sc[n][3];
        }
        l0 = l0 * c0 + ps0;
        l1 = l1 * c1 + ps1;
        #pragma unroll
        for (int n = 0; n < 8; n++) {
            ob[n][0] *= c0; ob[n][1] *= c0;
            ob[n][2] *= c1; ob[n][3] *= c1;
        }

        uint32_t pf[4][4];
        #pragma unroll
        for (int kb = 0; kb < 4; kb++) {
            pf[kb][0] = pk_bf(sc[2*kb  ][0], sc[2*kb  ][1]);
            pf[kb][1] = pk_bf(sc[2*kb  ][2], sc[2*kb  ][3]);
            pf[kb][2] = pk_bf(sc[2*kb+1][0], sc[2*kb+1][1]);
            pf[kb][3] = pk_bf(sc[2*kb+1][2], sc[2*kb+1][3]);
        }

        #pragma unroll
        for (int kb = 0; kb < 4; kb++) {
            #pragma unroll
            for (int np = 0; np < 4; np++) {
                uint32_t vd = (uint32_t)__cvta_generic_to_shared(
                    Vs + (kb * 16 + vrow) * ALD + np * 16 + vcol);
                uint32_t q[4];
                ldsm_x4_t(q, vd);
                uint32_t vb0[2] = {q[0], q[1]};
                uint32_t vb1[2] = {q[2], q[3]};
                mma_bf16(ob[np*2  ], pf[kb], vb0);
                mma_bf16(ob[np*2+1], pf[kb], vb1);
            }
        }
    }

    l0 += __shfl_xor_sync(0xffffffffu, l0, 1);
    l0 += __shfl_xor_sync(0xffffffffu, l0, 2);
    l1 += __shfl_xor_sync(0xffffffffu, l1, 1);
    l1 += __shfl_xor_sync(0xffffffffu, l1, 2);
    float inv0 = 1.f / l0, inv1 = 1.f / l1;

    int b = bh / H_, h = bh % H_;
    int r0 = q0 + w * 16 + g;
    __nv_bfloat16* o0 = O + ((size_t)(b * L_ + r0)) * D_ + h * DH_;
    __nv_bfloat16* o1 = O + ((size_t)(b * L_ + r0 + 8)) * D_ + h * DH_;
    #pragma unroll
    for (int n = 0; n < 8; n++) {
        *(__nv_bfloat162*)(o0 + n * 8 + 2 * t4) = __floats2bfloat162_rn(ob[n][0] * inv0, ob[n][1] * inv0);
        *(__nv_bfloat162*)(o1 + n * 8 + 2 * t4) = __floats2bfloat162_rn(ob[n][2] * inv1, ob[n][3] * inv1);
    }
}

// ---------------- host launcher ----------------
extern "C" void kernel_launch(void* const* d_in, const int* in_sizes, int n_in,
                              void* d_out, int out_size) {
    const float* x        = (const float*)d_in[0];
    const float* pos      = (const float*)d_in[1];
    const float* x_cross  = (const float*)d_in[2];
    const float* pos_cross= (const float*)d_in[3];
    const float* sa_norm  = (const float*)d_in[4];
    const float* sa_wqkv  = (const float*)d_in[5];
    const float* sa_scale = (const float*)d_in[6];
    const float* sa_wout  = (const float*)d_in[7];
    const float* ca_norm  = (const float*)d_in[8];
    const float* ca_normc = (const float*)d_in[9];
    const float* ca_wq    = (const float*)d_in[10];
    const float* ca_wkv   = (const float*)d_in[11];
    const float* ca_scale = (const float*)d_in[12];
    const float* ca_wout  = (const float*)d_in[13];
    const float* ff_norm  = (const float*)d_in[14];
    const float* ff_wup   = (const float*)d_in[15];
    const float* ff_wdown = (const float*)d_in[16];
    float* out = (float*)d_out;

    float *x1, *x2;
    __nv_bfloat16 *norm_bf, *normc_bf, *qkv_bf, *lin2_bf, *q_bf, *k_bf, *v_bf, *ao_bf, *ag_bf;
    __nv_bfloat16 *wqkv_bf, *wout1_bf, *wq_bf, *wkv_bf, *wout2_bf, *wup_bf, *wdown_bf;
    cudaGetSymbolAddress((void**)&x1, g_x1);
    cudaGetSymbolAddress((void**)&x2, g_x2);
    cudaGetSymbolAddress((void**)&norm_bf,  g_norm_bf);
    cudaGetSymbolAddress((void**)&normc_bf, g_normc_bf);
    cudaGetSymbolAddress((void**)&qkv_bf,   g_qkv_bf);
    cudaGetSymbolAddress((void**)&lin2_bf,  g_lin2_bf);
    cudaGetSymbolAddress((void**)&q_bf,     g_q_bf);
    cudaGetSymbolAddress((void**)&k_bf,     g_k_bf);
    cudaGetSymbolAddress((void**)&v_bf,     g_v_bf);
    cudaGetSymbolAddress((void**)&ao_bf,    g_ao_bf);
    cudaGetSymbolAddress((void**)&ag_bf,    g_ag_bf);
    cudaGetSymbolAddress((void**)&wqkv_bf,  g_wqkv_bf);
    cudaGetSymbolAddress((void**)&wout1_bf, g_wout1_bf);
    cudaGetSymbolAddress((void**)&wq_bf,    g_wq_bf);
    cudaGetSymbolAddress((void**)&wkv_bf,   g_wkv_bf);
    cudaGetSymbolAddress((void**)&wout2_bf, g_wout2_bf);
    cudaGetSymbolAddress((void**)&wup_bf,   g_wup_bf);
    cudaGetSymbolAddress((void**)&wdown_bf, g_wdown_bf);

    static bool attr_done = false;
    if (!attr_done) {
        cudaFuncSetAttribute((const void*)gemm_bf16<64,0>,  cudaFuncAttributeMaxDynamicSharedMemorySize, GSMEM(64));
        cudaFuncSetAttribute((const void*)gemm_bf16<64,1>,  cudaFuncAttributeMaxDynamicSharedMemorySize, GSMEM(64));
        cudaFuncSetAttribute((const void*)gemm_wide<1>, cudaFuncAttributeMaxDynamicSharedMemorySize, WGSMEM);
        cudaFuncSetAttribute((const void*)gemm_wide<2>, cudaFuncAttributeMaxDynamicSharedMemorySize, WGSMEM);
        cudaFuncSetAttribute((const void*)attn_bf, cudaFuncAttributeMaxDynamicSharedMemorySize, ATT_SMEM);
        attr_done = true;
    }

    // ---- weight conversion ----
    ConvTab t;
    t.src[0] = (const float4*)sa_wqkv;  t.dst[0] = (uint2*)wqkv_bf;  t.n4[0] = 2304*768/4;
    t.src[1] = (const float4*)sa_wout;  t.dst[1] = (uint2*)wout1_bf; t.n4[1] = 768*768/4;
    t.src[2] = (const float4*)ca_wq;    t.dst[2] = (uint2*)wq_bf;    t.n4[2] = 768*768/4;
    t.src[3] = (const float4*)ca_wkv;   t.dst[3] = (uint2*)wkv_bf;   t.n4[3] = 1536*768/4;
    t.src[4] = (const float4*)ca_wout;  t.dst[4] = (uint2*)wout2_bf; t.n4[4] = 768*768/4;
    t.src[5] = (const float4*)ff_wdown; t.dst[5] = (uint2*)wdown_bf; t.n4[5] = 768*2304/4;
    conv6_kernel<<<dim3((2304*768/4 + 255)/256, 6), 256>>>(t);
    convup_kernel<<<(UPN_*(D_/4) + 255)/256, 256>>>(ff_wup, wup_bf);

    const int packBlocks = (B_ * L_ * H_ * 2 * 32 + 255) / 256;

    // ---- self attention ----
    rmsnorm_kernel<<<M_, 256>>>(x, sa_norm, norm_bf);
    gemm_wide<1><<<dim3(2304/256, M_/128), 256, WGSMEM>>>(norm_bf, wqkv_bf, qkv_bf, M_, 2304, D_);
    qkv_pack<<<packBlocks, 256>>>(qkv_bf, 2304, 0, qkv_bf, 2304, 768, 1536,
                                  pos, pos, sa_scale, q_bf, k_bf, v_bf);
    attn_bf<<<dim3(L_/128, B_*H_), 256, ATT_SMEM>>>(q_bf, k_bf, v_bf, ao_bf);
    gemm_bf16<64,0><<<dim3(D_/128, M_/64), 256, GSMEM(64)>>>(ao_bf, wout1_bf, x, x1, nullptr, M_, D_, D_);

    // ---- cross attention ----
    rmsnorm2_kernel<<<dim3(M_, 2), 256>>>(x1, ca_norm, norm_bf, x_cross, ca_normc, normc_bf);
    gemm_bf16<64,1><<<dim3(D_/128, M_/64), 256, GSMEM(64)>>>(norm_bf,  wq_bf,  nullptr, nullptr, lin2_bf, M_, D_, D_);
    gemm_wide<1><<<dim3(1536/256, M_/128), 256, WGSMEM>>>(normc_bf, wkv_bf, qkv_bf, M_, 1536, D_);
    qkv_pack<<<packBlocks, 256>>>(lin2_bf, 768, 0, qkv_bf, 1536, 0, 768,
                                  pos, pos_cross, ca_scale, q_bf, k_bf, v_bf);
    attn_bf<<<dim3(L_/128, B_*H_), 256, ATT_SMEM>>>(q_bf, k_bf, v_bf, ao_bf);
    gemm_bf16<64,0><<<dim3(D_/128, M_/64), 256, GSMEM(64)>>>(ao_bf, wout2_bf, x1, x2, nullptr, M_, D_, D_);

    // ---- feed forward (silu fused in up-GEMM epilogue) ----
    rmsnorm_kernel<<<M_, 256>>>(x2, ff_norm, norm_bf);
    gemm_wide<2><<<dim3(UPN_/256, M_/128), 256, WGSMEM>>>(norm_bf, wup_bf, ag_bf, M_, UPN_, D_);
    gemm_bf16<64,0><<<dim3(D_/128, M_/64), 256, GSMEM(64)>>>(ag_bf, wdown_bf, x2, out, nullptr, M_, D_, DFF_);
}

// round 13
// speedup vs baseline: 1.0479x; 1.0479x over previous
#include <cuda_runtime.h>
#include <cuda_bf16.h>
#include <cstdint>

#define B_ 2
#define L_ 2048
#define D_ 768
#define H_ 12
#define DH_ 64
#define M_ (B_*L_)
#define DFF_ 2304
#define UPN_ (2*DFF_)

// ---------------- scratch ----------------
__device__ float g_x1 [M_*D_];
__device__ float g_x2 [M_*D_];

__device__ __nv_bfloat16 g_norm_bf [M_*D_];
__device__ __nv_bfloat16 g_normc_bf[M_*D_];
__device__ __nv_bfloat16 g_qkv_bf  [M_*2304];
__device__ __nv_bfloat16 g_lin2_bf [M_*D_];
__device__ __nv_bfloat16 g_q_bf    [B_*H_*L_*DH_];
__device__ __nv_bfloat16 g_k_bf    [B_*H_*L_*DH_];
__device__ __nv_bfloat16 g_v_bf    [B_*H_*L_*DH_];
__device__ __nv_bfloat16 g_ao_bf   [M_*D_];
__device__ __nv_bfloat16 g_ag_bf   [M_*DFF_];

__device__ __nv_bfloat16 g_wqkv_bf [2304*768];
__device__ __nv_bfloat16 g_wout1_bf[768*768];
__device__ __nv_bfloat16 g_wq_bf   [768*768];
__device__ __nv_bfloat16 g_wkv_bf  [1536*768];
__device__ __nv_bfloat16 g_wout2_bf[768*768];
__device__ __nv_bfloat16 g_wup_bf  [4608*768];   // permuted: row 2j=a_j, 2j+1=g_j
__device__ __nv_bfloat16 g_wdown_bf[768*2304];

// ---------------- mma / ldmatrix helpers ----------------
__device__ __forceinline__ void mma_bf16(float c[4], const uint32_t a[4], const uint32_t b[2]) {
    asm volatile("mma.sync.aligned.m16n8k16.row.col.f32.bf16.bf16.f32 "
                 "{%0,%1,%2,%3},{%4,%5,%6,%7},{%8,%9},{%0,%1,%2,%3};\n"
                 : "+f"(c[0]), "+f"(c[1]), "+f"(c[2]), "+f"(c[3])
                 : "r"(a[0]), "r"(a[1]), "r"(a[2]), "r"(a[3]), "r"(b[0]), "r"(b[1]));
}
__device__ __forceinline__ void ldsm_x4(uint32_t r[4], uint32_t addr) {
    asm volatile("ldmatrix.sync.aligned.m8n8.x4.shared.b16 {%0,%1,%2,%3}, [%4];"
                 : "=r"(r[0]), "=r"(r[1]), "=r"(r[2]), "=r"(r[3]) : "r"(addr));
}
__device__ __forceinline__ void ldsm_x4_t(uint32_t r[4], uint32_t addr) {
    asm volatile("ldmatrix.sync.aligned.m8n8.x4.trans.shared.b16 {%0,%1,%2,%3}, [%4];"
                 : "=r"(r[0]), "=r"(r[1]), "=r"(r[2]), "=r"(r[3]) : "r"(addr));
}
__device__ __forceinline__ uint32_t pk_bf(float a, float b) {
    __nv_bfloat162 t = __floats2bfloat162_rn(a, b);
    return *(uint32_t*)&t;
}

// ---------------- fused weight conversion ----------------
struct ConvTab {
    const float4* src[6];
    uint2*        dst[6];
    int           n4[6];
};
__global__ void conv6_kernel(ConvTab t) {
    int r = blockIdx.y;
    int i = blockIdx.x * 256 + threadIdx.x;
    if (i >= t.n4[r]) return;
    float4 v = t.src[r][i];
    __nv_bfloat162 lo = __floats2bfloat162_rn(v.x, v.y);
    __nv_bfloat162 hi = __floats2bfloat162_rn(v.z, v.w);
    uint2 o; o.x = *(uint32_t*)&lo; o.y = *(uint32_t*)&hi;
    t.dst[r][i] = o;
}
__global__ void convup_kernel(const float* __restrict__ src, __nv_bfloat16* __restrict__ dst) {
    int i = blockIdx.x * 256 + threadIdx.x;
    if (i >= UPN_ * (D_ / 4)) return;
    int p  = i / (D_ / 4);
    int kc = (i % (D_ / 4)) * 4;
    int srow = (p & 1) ? (DFF_ + (p >> 1)) : (p >> 1);
    float4 v = *(const float4*)(src + (size_t)srow * D_ + kc);
    __nv_bfloat162 lo = __floats2bfloat162_rn(v.x, v.y);
    __nv_bfloat162 hi = __floats2bfloat162_rn(v.z, v.w);
    uint2 o; o.x = *(uint32_t*)&lo; o.y = *(uint32_t*)&hi;
    *(uint2*)(dst + (size_t)p * D_ + kc) = o;
}

// ---------------- rmsnorm -> bf16 (single and dual-source) ----------------
__device__ __forceinline__ void rms_row(const float* xr, const float* sc,
                                        __nv_bfloat16* outr) {
    float s = 0.f;
    for (int i = threadIdx.x; i < D_; i += 256) { float v = xr[i]; s += v * v; }
    #pragma unroll
    for (int o = 16; o > 0; o >>= 1) s += __shfl_xor_sync(0xffffffffu, s, o);
    __shared__ float red[8];
    __shared__ float rtot;
    if ((threadIdx.x & 31) == 0) red[threadIdx.x >> 5] = s;
    __syncthreads();
    if (threadIdx.x == 0) {
        float t = 0.f;
        #pragma unroll
        for (int i = 0; i < 8; i++) t += red[i];
        rtot = rsqrtf(t / (float)D_ + 1e-6f);
    }
    __syncthreads();
    float r = rtot;
    for (int i = threadIdx.x; i < D_; i += 256)
        outr[i] = __float2bfloat16(xr[i] * sc[i] * r);
}
__global__ void rmsnorm_kernel(const float* __restrict__ x, const float* __restrict__ sc,
                               __nv_bfloat16* __restrict__ out) {
    int row = blockIdx.x;
    rms_row(x + (size_t)row * D_, sc, out + (size_t)row * D_);
}
__global__ void rmsnorm2_kernel(const float* __restrict__ xa, const float* __restrict__ sa,
                                __nv_bfloat16* __restrict__ oa,
                                const float* __restrict__ xb, const float* __restrict__ sb,
                                __nv_bfloat16* __restrict__ ob) {
    int row = blockIdx.x;
    if (blockIdx.y == 0) rms_row(xa + (size_t)row * D_, sa, oa + (size_t)row * D_);
    else                 rms_row(xb + (size_t)row * D_, sb, ob + (size_t)row * D_);
}

// ---------------- bf16 GEMM NT: BM x 128, BK=64, 3-stage, 1 barrier/iter ----
#define SLDH 72
#define GSMEM(BM) (3 * ((BM) + 128) * SLDH * 2)

template<int BM, int MODE>
__global__ __launch_bounds__(256, 2)
void gemm_bf16(const __nv_bfloat16* __restrict__ A,
               const __nv_bfloat16* __restrict__ Bw,
               const float* __restrict__ R,
               float* __restrict__ Cf,
               __nv_bfloat16* __restrict__ Cb,
               int M, int N, int K) {
    extern __shared__ __nv_bfloat16 smh[];
    constexpr int ATILE = BM * SLDH;
    constexpr int BTILE = 128 * SLDH;
    constexpr int MI = BM / 32;
    __nv_bfloat16* As = smh;
    __nv_bfloat16* Bs = smh + 3 * ATILE;

    const int tid = threadIdx.x;
    const int m0 = blockIdx.y * BM, n0 = blockIdx.x * 128;
    const int w = tid >> 5, lane = tid & 31;
    const int wm = w >> 2, wn = w & 3;
    const int g = lane >> 2, t4 = lane & 3;

    const int arow = (lane & 7) + ((lane >> 3) & 1) * 8;
    const int acol = (lane >> 4) * 8;
    const int brow = (lane & 7) + (lane >> 4) * 8;
    const int bcol = ((lane >> 3) & 1) * 8;

    float acc[MI][4][4];
    #pragma unroll
    for (int i = 0; i < MI; i++)
        #pragma unroll
        for (int j = 0; j < 4; j++)
            #pragma unroll
            for (int r = 0; r < 4; r++) acc[i][j][r] = 0.f;

    auto load_tiles = [&](int stage, int k0) {
        __nv_bfloat16* as = As + stage * ATILE;
        __nv_bfloat16* bs = Bs + stage * BTILE;
        #pragma unroll
        for (int i = 0; i < BM / 32; i++) {
            int id = tid + i * 256;
            int r = id >> 3, c = (id & 7) * 8;
            uint32_t sa = (uint32_t)__cvta_generic_to_shared(as + r * SLDH + c);
            const __nv_bfloat16* ga = A + (size_t)(m0 + r) * K + k0 + c;
            asm volatile("cp.async.cg.shared.global [%0], [%1], 16;\n" :: "r"(sa), "l"(ga));
        }
        #pragma unroll
        for (int i = 0; i < 4; i++) {
            int id = tid + i * 256;
            int r = id >> 3, c = (id & 7) * 8;
            uint32_t sb = (uint32_t)__cvta_generic_to_shared(bs + r * SLDH + c);
            const __nv_bfloat16* gb = Bw + (size_t)(n0 + r) * K + k0 + c;
            asm volatile("cp.async.cg.shared.global [%0], [%1], 16;\n" :: "r"(sb), "l"(gb));
        }
        asm volatile("cp.async.commit_group;\n");
    };

    const int numK = K >> 6;
    load_tiles(0, 0);
    load_tiles(1, 64);

    for (int kt = 0; kt < numK; kt++) {
        if (kt + 1 < numK) asm volatile("cp.async.wait_group 1;\n");
        else               asm volatile("cp.async.wait_group 0;\n");
        __syncthreads();
        if (kt + 2 < numK) load_tiles((kt + 2) % 3, (kt + 2) * 64);

        const __nv_bfloat16* as = As + (kt % 3) * ATILE;
        const __nv_bfloat16* bs = Bs + (kt % 3) * BTILE;

        #pragma unroll
        for (int kb = 0; kb < 4; kb++) {
            uint32_t af[MI][4], bf[4][2];
            #pragma unroll
            for (int mi = 0; mi < MI; mi++) {
                int mr = wm * (BM / 2) + mi * 16 + arow;
                uint32_t ad = (uint32_t)__cvta_generic_to_shared(as + mr * SLDH + kb * 16 + acol);
                ldsm_x4(af[mi], ad);
            }
            #pragma unroll
            for (int np = 0; np < 2; np++) {
                int nr = wn * 32 + np * 16 + brow;
                uint32_t bd = (uint32_t)__cvta_generic_to_shared(bs + nr * SLDH + kb * 16 + bcol);
                uint32_t q[4];
                ldsm_x4(q, bd);
                bf[np*2  ][0] = q[0]; bf[np*2  ][1] = q[1];
                bf[np*2+1][0] = q[2]; bf[np*2+1][1] = q[3];
            }
            #pragma unroll
            for (int mi = 0; mi < MI; mi++)
                #pragma unroll
                for (int ni = 0; ni < 4; ni++)
                    mma_bf16(acc[mi][ni], af[mi], bf[ni]);
        }
    }

    #pragma unroll
    for (int mi = 0; mi < MI; mi++) {
        int r0 = m0 + wm * (BM / 2) + mi * 16 + g;
        #pragma unroll
        for (int ni = 0; ni < 4; ni++) {
            int cc = n0 + wn * 32 + ni * 8 + 2 * t4;
            float a0 = acc[mi][ni][0], a1 = acc[mi][ni][1];
            float a2 = acc[mi][ni][2], a3 = acc[mi][ni][3];
            if (MODE == 0) {
                float2 r0v = *(const float2*)(R + (size_t)r0 * N + cc);
                float2 r1v = *(const float2*)(R + (size_t)(r0 + 8) * N + cc);
                *(float2*)(Cf + (size_t)r0 * N + cc)       = make_float2(a0 + r0v.x, a1 + r0v.y);
                *(float2*)(Cf + (size_t)(r0 + 8) * N + cc) = make_float2(a2 + r1v.x, a3 + r1v.y);
            } else if (MODE == 1) {
                *(__nv_bfloat162*)(Cb + (size_t)r0 * N + cc)       = __floats2bfloat162_rn(a0, a1);
                *(__nv_bfloat162*)(Cb + (size_t)(r0 + 8) * N + cc) = __floats2bfloat162_rn(a2, a3);
            } else {
                int jj = cc >> 1;
                float s0 = a0 * (a1 / (1.f + __expf(-a1)));
                float s1 = a2 * (a3 / (1.f + __expf(-a3)));
                Cb[(size_t)r0 * DFF_ + jj]       = __float2bfloat16(s0);
                Cb[(size_t)(r0 + 8) * DFF_ + jj] = __float2bfloat16(s1);
            }
        }
    }
}

// ---------------- fused q/k cos-scale+RoPE + v copy (2 warps per item) ------
__device__ __forceinline__ float theta_of(int j, int h, float p0, float p1, float p2) {
    int i = j >> 3, f = j & 7;
    float pc = (i == 0) ? p0 : ((i == 1) ? p1 : p2);
    float freq = 3.14159265358979f * __expf((float)(f * 12 + h) * 0.02398526136f);
    return pc * freq;
}

__device__ __forceinline__ void rope_vec(float* shrow, float v0, float v1,
                                         int lane, int h, float sscale,
                                         float p0, float p1, float p2,
                                         __nv_bfloat16* dst) {
    float ss = v0 * v0 + v1 * v1;
    #pragma unroll
    for (int o = 16; o > 0; o >>= 1) ss += __shfl_xor_sync(0xffffffffu, ss, o);
    float f = sscale * rsqrtf(ss + 1e-6f);
    shrow[lane] = v0 * f; shrow[lane + 32] = v1 * f;
    __syncwarp();

    float out0, out1;
    {
        int d = lane;
        if (d < 24) {
            float th = theta_of(d, h, p0, p1, p2);
            float s, c; __sincosf(th, &s, &c);
            out0 = shrow[d] * c - shrow[d + 24] * s;
        } else {
            float th = theta_of(d - 24, h, p0, p1, p2);
            float s, c; __sincosf(th, &s, &c);
            out0 = shrow[d] * c + shrow[d - 24] * s;
        }
    }
    {
        int d = lane + 32;
        if (d < 48) {
            float th = theta_of(d - 24, h, p0, p1, p2);
            float s, c; __sincosf(th, &s, &c);
            out1 = shrow[d] * c + shrow[d - 24] * s;
        } else {
            out1 = shrow[d];
        }
    }
    __syncwarp();
    dst[lane] = __float2bfloat16(out0);
    dst[lane + 32] = __float2bfloat16(out1);
}

__global__ void qkv_pack(const __nv_bfloat16* __restrict__ srcq, int strq, int offq,
                         const __nv_bfloat16* __restrict__ srck, int strk, int offk, int offv,
                         const float* __restrict__ posq, const float* __restrict__ posk,
                         const float* __restrict__ hscale,
                         __nv_bfloat16* __restrict__ dq, __nv_bfloat16* __restrict__ dk,
                         __nv_bfloat16* __restrict__ dv) {
    int gw = (blockIdx.x * blockDim.x + threadIdx.x) >> 5;
    int lane = threadIdx.x & 31;
    int item = gw >> 1, role = gw & 1;
    if (item >= B_ * L_ * H_) return;
    int h = item % H_;
    int bl = item / H_;
    int b = bl / L_, l = bl % L_;

    __shared__ float sh[8][64];
    float* shrow = sh[threadIdx.x >> 5];
    size_t hdst = ((size_t)(b * H_ + h) * L_ + l) * DH_;
    float s = sqrtf(hscale[h]);

    if (role == 0) {
        const __nv_bfloat16* sp = srcq + (size_t)bl * strq + offq + h * DH_;
        float v0 = __bfloat162float(sp[lane]), v1 = __bfloat162float(sp[lane + 32]);
        float p0 = posq[(size_t)bl * 3 + 0], p1 = posq[(size_t)bl * 3 + 1], p2 = posq[(size_t)bl * 3 + 2];
        rope_vec(shrow, v0, v1, lane, h, s, p0, p1, p2, dq + hdst);
    } else {
        const __nv_bfloat16* sp = srck + (size_t)bl * strk + offk + h * DH_;
        float v0 = __bfloat162float(sp[lane]), v1 = __bfloat162float(sp[lane + 32]);
        float p0 = posk[(size_t)bl * 3 + 0], p1 = posk[(size_t)bl * 3 + 1], p2 = posk[(size_t)bl * 3 + 2];
        rope_vec(shrow, v0, v1, lane, h, s, p0, p1, p2, dk + hdst);
        if (lane < 8) {
            *(uint4*)(dv + hdst + lane * 8) =
                *(const uint4*)(srck + (size_t)bl * strk + offv + h * DH_ + lane * 8);
        }
    }
}

// ---------------- bf16 flash attention, 3-stage cp.async KV pipeline ---------
#define ALD 72
#define ATT_STAGE (128 * ALD)
#define ATT_SMEM (3 * ATT_STAGE * 2)

__global__ __launch_bounds__(256, 2) void attn_bf(const __nv_bfloat16* __restrict__ Q,
                                                  const __nv_bfloat16* __restrict__ K,
                                                  const __nv_bfloat16* __restrict__ V,
                                                  __nv_bfloat16* __restrict__ O) {
    extern __shared__ __nv_bfloat16 KVs[];

    const int bh = blockIdx.y;
    const int q0 = blockIdx.x * 128;
    const int tid = threadIdx.x;
    const int w = tid >> 5, lane = tid & 31;
    const int g = lane >> 2, t4 = lane & 3;

    const int arow = (lane & 7) + ((lane >> 3) & 1) * 8;
    const int acol = (lane >> 4) * 8;
    const int brow = (lane & 7) + (lane >> 4) * 8;
    const int bcol = ((lane >> 3) & 1) * 8;
    const int vrow = (lane & 7) + ((lane >> 3) & 1) * 8;
    const int vcol = (lane >> 4) * 8;

    const __nv_bfloat16* qb = Q + ((size_t)bh * L_ + q0) * DH_;
    #pragma unroll
    for (int i = 0; i < 4; i++) {
        int idx = tid + i * 256;
        int r = idx >> 3, c = (idx & 7) * 8;
        *(uint4*)(KVs + r * ALD + c) = *(const uint4*)(qb + r * 64 + c);
    }
    __syncthreads();
    uint32_t qf[4][4];
    #pragma unroll
    for (int kb = 0; kb < 4; kb++) {
        uint32_t ad = (uint32_t)__cvta_generic_to_shared(
            KVs + (w * 16 + arow) * ALD + kb * 16 + acol);
        ldsm_x4(qf[kb], ad);
    }
    __syncthreads();

    const __nv_bfloat16* kbase = K + (size_t)bh * L_ * DH_;
    const __nv_bfloat16* vbase = V + (size_t)bh * L_ * DH_;

    auto load_kv = [&](int stage, int kt) {
        __nv_bfloat16* Ks = KVs + stage * ATT_STAGE;
        __nv_bfloat16* Vs = Ks + 64 * ALD;
        #pragma unroll
        for (int i = 0; i < 2; i++) {
            int idx = tid + i * 256;
            int r = idx >> 3, c = (idx & 7) * 8;
            uint32_t sk = (uint32_t)__cvta_generic_to_shared(Ks + r * ALD + c);
            asm volatile("cp.async.cg.shared.global [%0], [%1], 16;\n"
                         :: "r"(sk), "l"(kbase + (size_t)(kt + r) * 64 + c));
            uint32_t sv = (uint32_t)__cvta_generic_to_shared(Vs + r * ALD + c);
            asm volatile("cp.async.cg.shared.global [%0], [%1], 16;\n"
                         :: "r"(sv), "l"(vbase + (size_t)(kt + r) * 64 + c));
        }
        asm volatile("cp.async.commit_group;\n");
    };

    float ob[8][4];
    #pragma unroll
    for (int n = 0; n < 8; n++)
        #pragma unroll
        for (int r = 0; r < 4; r++) ob[n][r] = 0.f;
    float m0 = -1e30f, m1 = -1e30f, l0 = 0.f, l1 = 0.f;

    const int nt = L_ / 64;
    load_kv(0, 0);
    load_kv(1, 64);

    for (int t = 0; t < nt; t++) {
        if (t + 1 < nt) asm volatile("cp.async.wait_group 1;\n");
        else            asm volatile("cp.async.wait_group 0;\n");
        __syncthreads();
        if (t + 2 < nt) load_kv((t + 2) % 3, (t + 2) * 64);

        const __nv_bfloat16* Ks = KVs + (t % 3) * ATT_STAGE;
        const __nv_bfloat16* Vs = Ks + 64 * ALD;

        float sc[8][4];
        #pragma unroll
        for (int n = 0; n < 8; n++)
            #pragma unroll
            for (int r = 0; r < 4; r++) sc[n][r] = 0.f;
        #pragma unroll
        for (int kb = 0; kb < 4; kb++) {
            uint32_t bf[8][2];
            #pragma unroll
            for (int np = 0; np < 4; np++) {
                uint32_t bd = (uint32_t)__cvta_generic_to_shared(
                    Ks + (np * 16 + brow) * ALD + kb * 16 + bcol);
                uint32_t q[4];
                ldsm_x4(q, bd);
                bf[np*2  ][0] = q[0]; bf[np*2  ][1] = q[1];
                bf[np*2+1][0] = q[2]; bf[np*2+1][1] = q[3];
            }
            #pragma unroll
            for (int n = 0; n < 8; n++)
                mma_bf16(sc[n], qf[kb], bf[n]);
        }

        float rm0 = -1e30f, rm1 = -1e30f;
        #pragma unroll
        for (int n = 0; n < 8; n++) {
            rm0 = fmaxf(rm0, fmaxf(sc[n][0], sc[n][1]));
            rm1 = fmaxf(rm1, fmaxf(sc[n][2], sc[n][3]));
        }
        rm0 = fmaxf(rm0, __shfl_xor_sync(0xffffffffu, rm0, 1));
        rm0 = fmaxf(rm0, __shfl_xor_sync(0xffffffffu, rm0, 2));
        rm1 = fmaxf(rm1, __shfl_xor_sync(0xffffffffu, rm1, 1));
        rm1 = fmaxf(rm1, __shfl_xor_sync(0xffffffffu, rm1, 2));
        float nm0 = fmaxf(m0, rm0), nm1 = fmaxf(m1, rm1);
        float c0 = __expf(m0 - nm0), c1 = __expf(m1 - nm1);
        m0 = nm0; m1 = nm1;

        float ps0 = 0.f, ps1 = 0.f;
        #pragma unroll
        for (int n = 0; n < 8; n++) {
            sc[n][0] = __expf(sc[n][0] - nm0);
            sc[n][1] = __expf(sc[n][1] - nm0);
            sc[n][2] = __expf(sc[n][2] - nm1);
            sc[n][3] = __expf(sc[n][3] - nm1);
            ps0 += sc[n][0] + sc[n][1];
            ps1 += sc[n][2] + sc[n][3];
        }
        l0 = l0 * c0 + ps0;
        l1 = l1 * c1 + ps1;
        #pragma unroll
        for (int n = 0; n < 8; n++) {
            ob[n][0] *= c0; ob[n][1] *= c0;
            ob[n][2] *= c1; ob[n][3] *= c1;
        }

        uint32_t pf[4][4];
        #pragma unroll
        for (int kb = 0; kb < 4; kb++) {
            pf[kb][0] = pk_bf(sc[2*kb  ][0], sc[2*kb  ][1]);
            pf[kb][1] = pk_bf(sc[2*kb  ][2], sc[2*kb  ][3]);
            pf[kb][2] = pk_bf(sc[2*kb+1][0], sc[2*kb+1][1]);
            pf[kb][3] = pk_bf(sc[2*kb+1][2], sc[2*kb+1][3]);
        }

        #pragma unroll
        for (int kb = 0; kb < 4; kb++) {
            #pragma unroll
            for (int np = 0; np < 4; np++) {
                uint32_t vd = (uint32_t)__cvta_generic_to_shared(
                    Vs + (kb * 16 + vrow) * ALD + np * 16 + vcol);
                uint32_t q[4];
                ldsm_x4_t(q, vd);
                uint32_t vb0[2] = {q[0], q[1]};
                uint32_t vb1[2] = {q[2], q[3]};
                mma_bf16(ob[np*2  ], pf[kb], vb0);
                mma_bf16(ob[np*2+1], pf[kb], vb1);
            }
        }
    }

    l0 += __shfl_xor_sync(0xffffffffu, l0, 1);
    l0 += __shfl_xor_sync(0xffffffffu, l0, 2);
    l1 += __shfl_xor_sync(0xffffffffu, l1, 1);
    l1 += __shfl_xor_sync(0xffffffffu, l1, 2);
    float inv0 = 1.f / l0, inv1 = 1.f / l1;

    int b = bh / H_, h = bh % H_;
    int r0 = q0 + w * 16 + g;
    __nv_bfloat16* o0 = O + ((size_t)(b * L_ + r0)) * D_ + h * DH_;
    __nv_bfloat16* o1 = O + ((size_t)(b * L_ + r0 + 8)) * D_ + h * DH_;
    #pragma unroll
    for (int n = 0; n < 8; n++) {
        *(__nv_bfloat162*)(o0 + n * 8 + 2 * t4) = __floats2bfloat162_rn(ob[n][0] * inv0, ob[n][1] * inv0);
        *(__nv_bfloat162*)(o1 + n * 8 + 2 * t4) = __floats2bfloat162_rn(ob[n][2] * inv1, ob[n][3] * inv1);
    }
}

// ---------------- host launcher ----------------
extern "C" void kernel_launch(void* const* d_in, const int* in_sizes, int n_in,
                              void* d_out, int out_size) {
    const float* x        = (const float*)d_in[0];
    const float* pos      = (const float*)d_in[1];
    const float* x_cross  = (const float*)d_in[2];
    const float* pos_cross= (const float*)d_in[3];
    const float* sa_norm  = (const float*)d_in[4];
    const float* sa_wqkv  = (const float*)d_in[5];
    const float* sa_scale = (const float*)d_in[6];
    const float* sa_wout  = (const float*)d_in[7];
    const float* ca_norm  = (const float*)d_in[8];
    const float* ca_normc = (const float*)d_in[9];
    const float* ca_wq    = (const float*)d_in[10];
    const float* ca_wkv   = (const float*)d_in[11];
    const float* ca_scale = (const float*)d_in[12];
    const float* ca_wout  = (const float*)d_in[13];
    const float* ff_norm  = (const float*)d_in[14];
    const float* ff_wup   = (const float*)d_in[15];
    const float* ff_wdown = (const float*)d_in[16];
    float* out = (float*)d_out;

    float *x1, *x2;
    __nv_bfloat16 *norm_bf, *normc_bf, *qkv_bf, *lin2_bf, *q_bf, *k_bf, *v_bf, *ao_bf, *ag_bf;
    __nv_bfloat16 *wqkv_bf, *wout1_bf, *wq_bf, *wkv_bf, *wout2_bf, *wup_bf, *wdown_bf;
    cudaGetSymbolAddress((void**)&x1, g_x1);
    cudaGetSymbolAddress((void**)&x2, g_x2);
    cudaGetSymbolAddress((void**)&norm_bf,  g_norm_bf);
    cudaGetSymbolAddress((void**)&normc_bf, g_normc_bf);
    cudaGetSymbolAddress((void**)&qkv_bf,   g_qkv_bf);
    cudaGetSymbolAddress((void**)&lin2_bf,  g_lin2_bf);
    cudaGetSymbolAddress((void**)&q_bf,     g_q_bf);
    cudaGetSymbolAddress((void**)&k_bf,     g_k_bf);
    cudaGetSymbolAddress((void**)&v_bf,     g_v_bf);
    cudaGetSymbolAddress((void**)&ao_bf,    g_ao_bf);
    cudaGetSymbolAddress((void**)&ag_bf,    g_ag_bf);
    cudaGetSymbolAddress((void**)&wqkv_bf,  g_wqkv_bf);
    cudaGetSymbolAddress((void**)&wout1_bf, g_wout1_bf);
    cudaGetSymbolAddress((void**)&wq_bf,    g_wq_bf);
    cudaGetSymbolAddress((void**)&wkv_bf,   g_wkv_bf);
    cudaGetSymbolAddress((void**)&wout2_bf, g_wout2_bf);
    cudaGetSymbolAddress((void**)&wup_bf,   g_wup_bf);
    cudaGetSymbolAddress((void**)&wdown_bf, g_wdown_bf);

    static bool attr_done = false;
    if (!attr_done) {
        cudaFuncSetAttribute((const void*)gemm_bf16<128,1>, cudaFuncAttributeMaxDynamicSharedMemorySize, GSMEM(128));
        cudaFuncSetAttribute((const void*)gemm_bf16<128,2>, cudaFuncAttributeMaxDynamicSharedMemorySize, GSMEM(128));
        cudaFuncSetAttribute((const void*)gemm_bf16<64,0>,  cudaFuncAttributeMaxDynamicSharedMemorySize, GSMEM(64));
        cudaFuncSetAttribute((const void*)gemm_bf16<64,1>,  cudaFuncAttributeMaxDynamicSharedMemorySize, GSMEM(64));
        cudaFuncSetAttribute((const void*)attn_bf, cudaFuncAttributeMaxDynamicSharedMemorySize, ATT_SMEM);
        attr_done = true;
    }

    // ---- weight conversion ----
    ConvTab t;
    t.src[0] = (const float4*)sa_wqkv;  t.dst[0] = (uint2*)wqkv_bf;  t.n4[0] = 2304*768/4;
    t.src[1] = (const float4*)sa_wout;  t.dst[1] = (uint2*)wout1_bf; t.n4[1] = 768*768/4;
    t.src[2] = (const float4*)ca_wq;    t.dst[2] = (uint2*)wq_bf;    t.n4[2] = 768*768/4;
    t.src[3] = (const float4*)ca_wkv;   t.dst[3] = (uint2*)wkv_bf;   t.n4[3] = 1536*768/4;
    t.src[4] = (const float4*)ca_wout;  t.dst[4] = (uint2*)wout2_bf; t.n4[4] = 768*768/4;
    t.src[5] = (const float4*)ff_wdown; t.dst[5] = (uint2*)wdown_bf; t.n4[5] = 768*2304/4;
    conv6_kernel<<<dim3((2304*768/4 + 255)/256, 6), 256>>>(t);
    convup_kernel<<<(UPN_*(D_/4) + 255)/256, 256>>>(ff_wup, wup_bf);

    const int packBlocks = (B_ * L_ * H_ * 2 * 32 + 255) / 256;

    // ---- self attention ----
    rmsnorm_kernel<<<M_, 256>>>(x, sa_norm, norm_bf);
    gemm_bf16<128,1><<<dim3(2304/128, M_/128), 256, GSMEM(128)>>>(norm_bf, wqkv_bf, nullptr, nullptr, qkv_bf, M_, 2304, D_);
    qkv_pack<<<packBlocks, 256>>>(qkv_bf, 2304, 0, qkv_bf, 2304, 768, 1536,
                                  pos, pos, sa_scale, q_bf, k_bf, v_bf);
    attn_bf<<<dim3(L_/128, B_*H_), 256, ATT_SMEM>>>(q_bf, k_bf, v_bf, ao_bf);
    gemm_bf16<64,0><<<dim3(D_/128, M_/64), 256, GSMEM(64)>>>(ao_bf, wout1_bf, x, x1, nullptr, M_, D_, D_);

    // ---- cross attention ----
    rmsnorm2_kernel<<<dim3(M_, 2), 256>>>(x1, ca_norm, norm_bf, x_cross, ca_normc, normc_bf);
    gemm_bf16<64,1><<<dim3(D_/128, M_/64), 256, GSMEM(64)>>>(norm_bf,  wq_bf,  nullptr, nullptr, lin2_bf, M_, D_, D_);
    gemm_bf16<128,1><<<dim3(1536/128, M_/128), 256, GSMEM(128)>>>(normc_bf, wkv_bf, nullptr, nullptr, qkv_bf, M_, 1536, D_);
    qkv_pack<<<packBlocks, 256>>>(lin2_bf, 768, 0, qkv_bf, 1536, 0, 768,
                                  pos, pos_cross, ca_scale, q_bf, k_bf, v_bf);
    attn_bf<<<dim3(L_/128, B_*H_), 256, ATT_SMEM>>>(q_bf, k_bf, v_bf, ao_bf);
    gemm_bf16<64,0><<<dim3(D_/128, M_/64), 256, GSMEM(64)>>>(ao_bf, wout2_bf, x1, x2, nullptr, M_, D_, D_);

    // ---- feed forward (silu fused in up-GEMM epilogue) ----
    rmsnorm_kernel<<<M_, 256>>>(x2, ff_norm, norm_bf);
    gemm_bf16<128,2><<<dim3(UPN_/128, M_/128), 256, GSMEM(128)>>>(norm_bf, wup_bf, nullptr, nullptr, ag_bf, M_, UPN_, D_);
    gemm_bf16<64,0><<<dim3(D_/128, M_/64), 256, GSMEM(64)>>>(ag_bf, wdown_bf, x2, out, nullptr, M_, D_, DFF_);
}

// round 15
// speedup vs baseline: 1.0886x; 1.0388x over previous
#include <cuda_runtime.h>
#include <cuda_bf16.h>
#include <cstdint>

#define B_ 2
#define L_ 2048
#define D_ 768
#define H_ 12
#define DH_ 64
#define M_ (B_*L_)
#define DFF_ 2304
#define UPN_ (2*DFF_)

// ---------------- scratch ----------------
__device__ float g_x1 [M_*D_];
__device__ float g_x2 [M_*D_];

__device__ __nv_bfloat16 g_norm_bf [M_*D_];
__device__ __nv_bfloat16 g_normc_bf[M_*D_];
__device__ __nv_bfloat16 g_qkv_bf  [M_*2304];
__device__ __nv_bfloat16 g_lin2_bf [M_*D_];
__device__ __nv_bfloat16 g_q_bf    [B_*H_*L_*DH_];
__device__ __nv_bfloat16 g_k_bf    [B_*H_*L_*DH_];
__device__ __nv_bfloat16 g_v_bf    [B_*H_*L_*DH_];
__device__ __nv_bfloat16 g_ao_bf   [M_*D_];
__device__ __nv_bfloat16 g_ag_bf   [M_*DFF_];

__device__ __nv_bfloat16 g_wqkv_bf [2304*768];
__device__ __nv_bfloat16 g_wout1_bf[768*768];
__device__ __nv_bfloat16 g_wq_bf   [768*768];
__device__ __nv_bfloat16 g_wkv_bf  [1536*768];
__device__ __nv_bfloat16 g_wout2_bf[768*768];
__device__ __nv_bfloat16 g_wup_bf  [4608*768];   // permuted: row 2j=a_j, 2j+1=g_j
__device__ __nv_bfloat16 g_wdown_bf[768*2304];

// ---------------- mma / ldmatrix helpers ----------------
__device__ __forceinline__ void mma_bf16(float c[4], const uint32_t a[4], const uint32_t b[2]) {
    asm volatile("mma.sync.aligned.m16n8k16.row.col.f32.bf16.bf16.f32 "
                 "{%0,%1,%2,%3},{%4,%5,%6,%7},{%8,%9},{%0,%1,%2,%3};\n"
                 : "+f"(c[0]), "+f"(c[1]), "+f"(c[2]), "+f"(c[3])
                 : "r"(a[0]), "r"(a[1]), "r"(a[2]), "r"(a[3]), "r"(b[0]), "r"(b[1]));
}
__device__ __forceinline__ void ldsm_x4(uint32_t r[4], uint32_t addr) {
    asm volatile("ldmatrix.sync.aligned.m8n8.x4.shared.b16 {%0,%1,%2,%3}, [%4];"
                 : "=r"(r[0]), "=r"(r[1]), "=r"(r[2]), "=r"(r[3]) : "r"(addr));
}
__device__ __forceinline__ void ldsm_x4_t(uint32_t r[4], uint32_t addr) {
    asm volatile("ldmatrix.sync.aligned.m8n8.x4.trans.shared.b16 {%0,%1,%2,%3}, [%4];"
                 : "=r"(r[0]), "=r"(r[1]), "=r"(r[2]), "=r"(r[3]) : "r"(addr));
}
__device__ __forceinline__ uint32_t pk_bf(float a, float b) {
    __nv_bfloat162 t = __floats2bfloat162_rn(a, b);
    return *(uint32_t*)&t;
}

// ---------------- weight conversion ----------------
struct ConvTab {
    const float4* src[5];
    uint2*        dst[5];
    int           n4[5];
};
__global__ void conv5_kernel(ConvTab t) {
    int r = blockIdx.y;
    int i = blockIdx.x * 256 + threadIdx.x;
    if (i >= t.n4[r]) return;
    float4 v = t.src[r][i];
    __nv_bfloat162 lo = __floats2bfloat162_rn(v.x, v.y);
    __nv_bfloat162 hi = __floats2bfloat162_rn(v.z, v.w);
    uint2 o; o.x = *(uint32_t*)&lo; o.y = *(uint32_t*)&hi;
    t.dst[r][i] = o;
}
__global__ void conv1_kernel(const float4* __restrict__ src, uint2* __restrict__ dst, int n4) {
    int i = blockIdx.x * 256 + threadIdx.x;
    if (i >= n4) return;
    float4 v = src[i];
    __nv_bfloat162 lo = __floats2bfloat162_rn(v.x, v.y);
    __nv_bfloat162 hi = __floats2bfloat162_rn(v.z, v.w);
    uint2 o; o.x = *(uint32_t*)&lo; o.y = *(uint32_t*)&hi;
    dst[i] = o;
}
__global__ void convup_kernel(const float* __restrict__ src, __nv_bfloat16* __restrict__ dst) {
    int i = blockIdx.x * 256 + threadIdx.x;
    if (i >= UPN_ * (D_ / 4)) return;
    int p  = i / (D_ / 4);
    int kc = (i % (D_ / 4)) * 4;
    int srow = (p & 1) ? (DFF_ + (p >> 1)) : (p >> 1);
    float4 v = *(const float4*)(src + (size_t)srow * D_ + kc);
    __nv_bfloat162 lo = __floats2bfloat162_rn(v.x, v.y);
    __nv_bfloat162 hi = __floats2bfloat162_rn(v.z, v.w);
    uint2 o; o.x = *(uint32_t*)&lo; o.y = *(uint32_t*)&hi;
    *(uint2*)(dst + (size_t)p * D_ + kc) = o;
}

// ---------------- rmsnorm -> bf16 ----------------
__global__ void rmsnorm_kernel(const float* __restrict__ x, const float* __restrict__ sc,
                               __nv_bfloat16* __restrict__ out) {
    int row = blockIdx.x;
    const float* xr = x + (size_t)row * D_;
    float s = 0.f;
    for (int i = threadIdx.x; i < D_; i += 256) { float v = xr[i]; s += v * v; }
    #pragma unroll
    for (int o = 16; o > 0; o >>= 1) s += __shfl_xor_sync(0xffffffffu, s, o);
    __shared__ float red[8];
    __shared__ float rtot;
    if ((threadIdx.x & 31) == 0) red[threadIdx.x >> 5] = s;
    __syncthreads();
    if (threadIdx.x == 0) {
        float t = 0.f;
        #pragma unroll
        for (int i = 0; i < 8; i++) t += red[i];
        rtot = rsqrtf(t / (float)D_ + 1e-6f);
    }
    __syncthreads();
    float r = rtot;
    for (int i = threadIdx.x; i < D_; i += 256)
        out[(size_t)row * D_ + i] = __float2bfloat16(xr[i] * sc[i] * r);
}

// ---------------- bf16 GEMM NT: BM x 128, BK=64, 3-stage, 1 barrier/iter ----
#define SLDH 72
#define GSMEM(BM) (3 * ((BM) + 128) * SLDH * 2)

template<int BM, int MODE>
__global__ __launch_bounds__(256, 2)
void gemm_bf16(const __nv_bfloat16* __restrict__ A,
               const __nv_bfloat16* __restrict__ Bw,
               const float* __restrict__ R,
               float* __restrict__ Cf,
               __nv_bfloat16* __restrict__ Cb,
               int M, int N, int K) {
    extern __shared__ __nv_bfloat16 smh[];
    constexpr int ATILE = BM * SLDH;
    constexpr int BTILE = 128 * SLDH;
    constexpr int MI = BM / 32;
    __nv_bfloat16* As = smh;
    __nv_bfloat16* Bs = smh + 3 * ATILE;

    const int tid = threadIdx.x;
    const int m0 = blockIdx.y * BM, n0 = blockIdx.x * 128;
    const int w = tid >> 5, lane = tid & 31;
    const int wm = w >> 2, wn = w & 3;
    const int g = lane >> 2, t4 = lane & 3;

    const int arow = (lane & 7) + ((lane >> 3) & 1) * 8;
    const int acol = (lane >> 4) * 8;
    const int brow = (lane & 7) + (lane >> 4) * 8;
    const int bcol = ((lane >> 3) & 1) * 8;

    float acc[MI][4][4];
    #pragma unroll
    for (int i = 0; i < MI; i++)
        #pragma unroll
        for (int j = 0; j < 4; j++)
            #pragma unroll
            for (int r = 0; r < 4; r++) acc[i][j][r] = 0.f;

    auto load_tiles = [&](int stage, int k0) {
        __nv_bfloat16* as = As + stage * ATILE;
        __nv_bfloat16* bs = Bs + stage * BTILE;
        #pragma unroll
        for (int i = 0; i < BM / 32; i++) {
            int id = tid + i * 256;
            int r = id >> 3, c = (id & 7) * 8;
            uint32_t sa = (uint32_t)__cvta_generic_to_shared(as + r * SLDH + c);
            const __nv_bfloat16* ga = A + (size_t)(m0 + r) * K + k0 + c;
            asm volatile("cp.async.cg.shared.global [%0], [%1], 16;\n" :: "r"(sa), "l"(ga));
        }
        #pragma unroll
        for (int i = 0; i < 4; i++) {
            int id = tid + i * 256;
            int r = id >> 3, c = (id & 7) * 8;
            uint32_t sb = (uint32_t)__cvta_generic_to_shared(bs + r * SLDH + c);
            const __nv_bfloat16* gb = Bw + (size_t)(n0 + r) * K + k0 + c;
            asm volatile("cp.async.cg.shared.global [%0], [%1], 16;\n" :: "r"(sb), "l"(gb));
        }
        asm volatile("cp.async.commit_group;\n");
    };

    const int numK = K >> 6;
    load_tiles(0, 0);
    load_tiles(1, 64);

    for (int kt = 0; kt < numK; kt++) {
        if (kt + 1 < numK) asm volatile("cp.async.wait_group 1;\n");
        else               asm volatile("cp.async.wait_group 0;\n");
        __syncthreads();
        if (kt + 2 < numK) load_tiles((kt + 2) % 3, (kt + 2) * 64);

        const __nv_bfloat16* as = As + (kt % 3) * ATILE;
        const __nv_bfloat16* bs = Bs + (kt % 3) * BTILE;

        #pragma unroll
        for (int kb = 0; kb < 4; kb++) {
            uint32_t af[MI][4], bf[4][2];
            #pragma unroll
            for (int mi = 0; mi < MI; mi++) {
                int mr = wm * (BM / 2) + mi * 16 + arow;
                uint32_t ad = (uint32_t)__cvta_generic_to_shared(as + mr * SLDH + kb * 16 + acol);
                ldsm_x4(af[mi], ad);
            }
            #pragma unroll
            for (int np = 0; np < 2; np++) {
                int nr = wn * 32 + np * 16 + brow;
                uint32_t bd = (uint32_t)__cvta_generic_to_shared(bs + nr * SLDH + kb * 16 + bcol);
                uint32_t q[4];
                ldsm_x4(q, bd);
                bf[np*2  ][0] = q[0]; bf[np*2  ][1] = q[1];
                bf[np*2+1][0] = q[2]; bf[np*2+1][1] = q[3];
            }
            #pragma unroll
            for (int mi = 0; mi < MI; mi++)
                #pragma unroll
                for (int ni = 0; ni < 4; ni++)
                    mma_bf16(acc[mi][ni], af[mi], bf[ni]);
        }
    }

    #pragma unroll
    for (int mi = 0; mi < MI; mi++) {
        int r0 = m0 + wm * (BM / 2) + mi * 16 + g;
        #pragma unroll
        for (int ni = 0; ni < 4; ni++) {
            int cc = n0 + wn * 32 + ni * 8 + 2 * t4;
            float a0 = acc[mi][ni][0], a1 = acc[mi][ni][1];
            float a2 = acc[mi][ni][2], a3 = acc[mi][ni][3];
            if (MODE == 0) {
                float2 r0v = *(const float2*)(R + (size_t)r0 * N + cc);
                float2 r1v = *(const float2*)(R + (size_t)(r0 + 8) * N + cc);
                *(float2*)(Cf + (size_t)r0 * N + cc)       = make_float2(a0 + r0v.x, a1 + r0v.y);
                *(float2*)(Cf + (size_t)(r0 + 8) * N + cc) = make_float2(a2 + r1v.x, a3 + r1v.y);
            } else if (MODE == 1) {
                *(__nv_bfloat162*)(Cb + (size_t)r0 * N + cc)       = __floats2bfloat162_rn(a0, a1);
                *(__nv_bfloat162*)(Cb + (size_t)(r0 + 8) * N + cc) = __floats2bfloat162_rn(a2, a3);
            } else {
                int jj = cc >> 1;
                float s0 = a0 * (a1 / (1.f + __expf(-a1)));
                float s1 = a2 * (a3 / (1.f + __expf(-a3)));
                Cb[(size_t)r0 * DFF_ + jj]       = __float2bfloat16(s0);
                Cb[(size_t)(r0 + 8) * DFF_ + jj] = __float2bfloat16(s1);
            }
        }
    }
}

// ---------------- fused q/k cos-scale+RoPE + v copy (one warp per item) -----
__device__ __forceinline__ float theta_of(int j, int h, float p0, float p1, float p2) {
    int i = j >> 3, f = j & 7;
    float pc = (i == 0) ? p0 : ((i == 1) ? p1 : p2);
    float freq = 3.14159265358979f * __expf((float)(f * 12 + h) * 0.02398526136f);
    return pc * freq;
}

__device__ __forceinline__ void rope_vec(float* shrow, float v0, float v1,
                                         int lane, int h, float sscale,
                                         float p0, float p1, float p2,
                                         __nv_bfloat16* dst) {
    float ss = v0 * v0 + v1 * v1;
    #pragma unroll
    for (int o = 16; o > 0; o >>= 1) ss += __shfl_xor_sync(0xffffffffu, ss, o);
    float f = sscale * rsqrtf(ss + 1e-6f);
    shrow[lane] = v0 * f; shrow[lane + 32] = v1 * f;
    __syncwarp();

    float out0, out1;
    {
        int d = lane;
        if (d < 24) {
            float th = theta_of(d, h, p0, p1, p2);
            float s, c; __sincosf(th, &s, &c);
            out0 = shrow[d] * c - shrow[d + 24] * s;
        } else {
            float th = theta_of(d - 24, h, p0, p1, p2);
            float s, c; __sincosf(th, &s, &c);
            out0 = shrow[d] * c + shrow[d - 24] * s;
        }
    }
    {
        int d = lane + 32;
        if (d < 48) {
            float th = theta_of(d - 24, h, p0, p1, p2);
            float s, c; __sincosf(th, &s, &c);
            out1 = shrow[d] * c + shrow[d - 24] * s;
        } else {
            out1 = shrow[d];
        }
    }
    __syncwarp();
    dst[lane] = __float2bfloat16(out0);
    dst[lane + 32] = __float2bfloat16(out1);
}

__global__ void qkv_pack(const __nv_bfloat16* __restrict__ srcq, int strq, int offq,
                         const __nv_bfloat16* __restrict__ srck, int strk, int offk, int offv,
                         const float* __restrict__ posq, const float* __restrict__ posk,
                         const float* __restrict__ hscale,
                         __nv_bfloat16* __restrict__ dq, __nv_bfloat16* __restrict__ dk,
                         __nv_bfloat16* __restrict__ dv) {
    int wg = (blockIdx.x * blockDim.x + threadIdx.x) >> 5;
    int lane = threadIdx.x & 31;
    if (wg >= B_ * L_ * H_) return;
    int h = wg % H_;
    int bl = wg / H_;
    int b = bl / L_, l = bl % L_;

    __shared__ float sh[8][64];
    float* shrow = sh[threadIdx.x >> 5];
    size_t hdst = ((size_t)(b * H_ + h) * L_ + l) * DH_;
    float s = sqrtf(hscale[h]);

    {
        const __nv_bfloat16* sp = srcq + (size_t)bl * strq + offq + h * DH_;
        float v0 = __bfloat162float(sp[lane]), v1 = __bfloat162float(sp[lane + 32]);
        float p0 = posq[(size_t)bl * 3 + 0], p1 = posq[(size_t)bl * 3 + 1], p2 = posq[(size_t)bl * 3 + 2];
        rope_vec(shrow, v0, v1, lane, h, s, p0, p1, p2, dq + hdst);
    }
    {
        const __nv_bfloat16* sp = srck + (size_t)bl * strk + offk + h * DH_;
        float v0 = __bfloat162float(sp[lane]), v1 = __bfloat162float(sp[lane + 32]);
        float p0 = posk[(size_t)bl * 3 + 0], p1 = posk[(size_t)bl * 3 + 1], p2 = posk[(size_t)bl * 3 + 2];
        rope_vec(shrow, v0, v1, lane, h, s, p0, p1, p2, dk + hdst);
    }
    if (lane < 8) {
        *(uint4*)(dv + hdst + lane * 8) =
            *(const uint4*)(srck + (size_t)bl * strk + offv + h * DH_ + lane * 8);
    }
}

// ---------------- bf16 flash attention, 3-stage cp.async KV pipeline ---------
#define ALD 72
#define ATT_STAGE (128 * ALD)
#define ATT_SMEM (3 * ATT_STAGE * 2)

__global__ __launch_bounds__(256, 2) void attn_bf(const __nv_bfloat16* __restrict__ Q,
                                                  const __nv_bfloat16* __restrict__ K,
                                                  const __nv_bfloat16* __restrict__ V,
                                                  __nv_bfloat16* __restrict__ O) {
    extern __shared__ __nv_bfloat16 KVs[];

    const int bh = blockIdx.y;
    const int q0 = blockIdx.x * 128;
    const int tid = threadIdx.x;
    const int w = tid >> 5, lane = tid & 31;
    const int g = lane >> 2, t4 = lane & 3;

    const int arow = (lane & 7) + ((lane >> 3) & 1) * 8;
    const int acol = (lane >> 4) * 8;
    const int brow = (lane & 7) + (lane >> 4) * 8;
    const int bcol = ((lane >> 3) & 1) * 8;
    const int vrow = (lane & 7) + ((lane >> 3) & 1) * 8;
    const int vcol = (lane >> 4) * 8;

    const __nv_bfloat16* qb = Q + ((size_t)bh * L_ + q0) * DH_;
    #pragma unroll
    for (int i = 0; i < 4; i++) {
        int idx = tid + i * 256;
        int r = idx >> 3, c = (idx & 7) * 8;
        *(uint4*)(KVs + r * ALD + c) = *(const uint4*)(qb + r * 64 + c);
    }
    __syncthreads();
    uint32_t qf[4][4];
    #pragma unroll
    for (int kb = 0; kb < 4; kb++) {
        uint32_t ad = (uint32_t)__cvta_generic_to_shared(
            KVs + (w * 16 + arow) * ALD + kb * 16 + acol);
        ldsm_x4(qf[kb], ad);
    }
    __syncthreads();

    const __nv_bfloat16* kbase = K + (size_t)bh * L_ * DH_;
    const __nv_bfloat16* vbase = V + (size_t)bh * L_ * DH_;

    auto load_kv = [&](int stage, int kt) {
        __nv_bfloat16* Ks = KVs + stage * ATT_STAGE;
        __nv_bfloat16* Vs = Ks + 64 * ALD;
        #pragma unroll
        for (int i = 0; i < 2; i++) {
            int idx = tid + i * 256;
            int r = idx >> 3, c = (idx & 7) * 8;
            uint32_t sk = (uint32_t)__cvta_generic_to_shared(Ks + r * ALD + c);
            asm volatile("cp.async.cg.shared.global [%0], [%1], 16;\n"
                         :: "r"(sk), "l"(kbase + (size_t)(kt + r) * 64 + c));
            uint32_t sv = (uint32_t)__cvta_generic_to_shared(Vs + r * ALD + c);
            asm volatile("cp.async.cg.shared.global [%0], [%1], 16;\n"
                         :: "r"(sv), "l"(vbase + (size_t)(kt + r) * 64 + c));
        }
        asm volatile("cp.async.commit_group;\n");
    };

    float ob[8][4];
    #pragma unroll
    for (int n = 0; n < 8; n++)
        #pragma unroll
        for (int r = 0; r < 4; r++) ob[n][r] = 0.f;
    float m0 = -1e30f, m1 = -1e30f, l0 = 0.f, l1 = 0.f;

    const int nt = L_ / 64;
    load_kv(0, 0);
    load_kv(1, 64);

    for (int t = 0; t < nt; t++) {
        if (t + 1 < nt) asm volatile("cp.async.wait_group 1;\n");
        else            asm volatile("cp.async.wait_group 0;\n");
        __syncthreads();
        if (t + 2 < nt) load_kv((t + 2) % 3, (t + 2) * 64);

        const __nv_bfloat16* Ks = KVs + (t % 3) * ATT_STAGE;
        const __nv_bfloat16* Vs = Ks + 64 * ALD;

        float sc[8][4];
        #pragma unroll
        for (int n = 0; n < 8; n++)
            #pragma unroll
            for (int r = 0; r < 4; r++) sc[n][r] = 0.f;
        #pragma unroll
        for (int kb = 0; kb < 4; kb++) {
            uint32_t bf[8][2];
            #pragma unroll
            for (int np = 0; np < 4; np++) {
                uint32_t bd = (uint32_t)__cvta_generic_to_shared(
                    Ks + (np * 16 + brow) * ALD + kb * 16 + bcol);
                uint32_t q[4];
                ldsm_x4(q, bd);
                bf[np*2  ][0] = q[0]; bf[np*2  ][1] = q[1];
                bf[np*2+1][0] = q[2]; bf[np*2+1][1] = q[3];
            }
            #pragma unroll
            for (int n = 0; n < 8; n++)
                mma_bf16(sc[n], qf[kb], bf[n]);
        }

        float rm0 = -1e30f, rm1 = -1e30f;
        #pragma unroll
        for (int n = 0; n < 8; n++) {
            rm0 = fmaxf(rm0, fmaxf(sc[n][0], sc[n][1]));
            rm1 = fmaxf(rm1, fmaxf(sc[n][2], sc[n][3]));
        }
        rm0 = fmaxf(rm0, __shfl_xor_sync(0xffffffffu, rm0, 1));
        rm0 = fmaxf(rm0, __shfl_xor_sync(0xffffffffu, rm0, 2));
        rm1 = fmaxf(rm1, __shfl_xor_sync(0xffffffffu, rm1, 1));
        rm1 = fmaxf(rm1, __shfl_xor_sync(0xffffffffu, rm1, 2));
        float nm0 = fmaxf(m0, rm0), nm1 = fmaxf(m1, rm1);
        float c0 = __expf(m0 - nm0), c1 = __expf(m1 - nm1);
        m0 = nm0; m1 = nm1;

        float ps0 = 0.f, ps1 = 0.f;
        #pragma unroll
        for (int n = 0; n < 8; n++) {
            sc[n][0] = __expf(sc[n][0] - nm0);
            sc[n][1] = __expf(sc[n][1] - nm0);
            sc[n][2] = __expf(sc[n][2] - nm1);
            sc[n][3] = __expf(sc[n][3] - nm1);
            ps0 += sc[n][0] + sc[n][1];
            ps1 += sc[n][2] + sc[n][3];
        }
        l0 = l0 * c0 + ps0;
        l1 = l1 * c1 + ps1;
        #pragma unroll
        for (int n = 0; n < 8; n++) {
            ob[n][0] *= c0; ob[n][1] *= c0;
            ob[n][2] *= c1; ob[n][3] *= c1;
        }

        uint32_t pf[4][4];
        #pragma unroll
        for (int kb = 0; kb < 4; kb++) {
            pf[kb][0] = pk_bf(sc[2*kb  ][0], sc[2*kb  ][1]);
            pf[kb][1] = pk_bf(sc[2*kb  ][2], sc[2*kb  ][3]);
            pf[kb][2] = pk_bf(sc[2*kb+1][0], sc[2*kb+1][1]);
            pf[kb][3] = pk_bf(sc[2*kb+1][2], sc[2*kb+1][3]);
        }

        #pragma unroll
        for (int kb = 0; kb < 4; kb++) {
            #pragma unroll
            for (int np = 0; np < 4; np++) {
                uint32_t vd = (uint32_t)__cvta_generic_to_shared(
                    Vs + (kb * 16 + vrow) * ALD + np * 16 + vcol);
                uint32_t q[4];
                ldsm_x4_t(q, vd);
                uint32_t vb0[2] = {q[0], q[1]};
                uint32_t vb1[2] = {q[2], q[3]};
                mma_bf16(ob[np*2  ], pf[kb], vb0);
                mma_bf16(ob[np*2+1], pf[kb], vb1);
            }
        }
    }

    l0 += __shfl_xor_sync(0xffffffffu, l0, 1);
    l0 += __shfl_xor_sync(0xffffffffu, l0, 2);
    l1 += __shfl_xor_sync(0xffffffffu, l1, 1);
    l1 += __shfl_xor_sync(0xffffffffu, l1, 2);
    float inv0 = 1.f / l0, inv1 = 1.f / l1;

    int b = bh / H_, h = bh % H_;
    int r0 = q0 + w * 16 + g;
    __nv_bfloat16* o0 = O + ((size_t)(b * L_ + r0)) * D_ + h * DH_;
    __nv_bfloat16* o1 = O + ((size_t)(b * L_ + r0 + 8)) * D_ + h * DH_;
    #pragma unroll
    for (int n = 0; n < 8; n++) {
        *(__nv_bfloat162*)(o0 + n * 8 + 2 * t4) = __floats2bfloat162_rn(ob[n][0] * inv0, ob[n][1] * inv0);
        *(__nv_bfloat162*)(o1 + n * 8 + 2 * t4) = __floats2bfloat162_rn(ob[n][2] * inv1, ob[n][3] * inv1);
    }
}

// ---------------- host launcher ----------------
extern "C" void kernel_launch(void* const* d_in, const int* in_sizes, int n_in,
                              void* d_out, int out_size) {
    const float* x        = (const float*)d_in[0];
    const float* pos      = (const float*)d_in[1];
    const float* x_cross  = (const float*)d_in[2];
    const float* pos_cross= (const float*)d_in[3];
    const float* sa_norm  = (const float*)d_in[4];
    const float* sa_wqkv  = (const float*)d_in[5];
    const float* sa_scale = (const float*)d_in[6];
    const float* sa_wout  = (const float*)d_in[7];
    const float* ca_norm  = (const float*)d_in[8];
    const float* ca_normc = (const float*)d_in[9];
    const float* ca_wq    = (const float*)d_in[10];
    const float* ca_wkv   = (const float*)d_in[11];
    const float* ca_scale = (const float*)d_in[12];
    const float* ca_wout  = (const float*)d_in[13];
    const float* ff_norm  = (const float*)d_in[14];
    const float* ff_wup   = (const float*)d_in[15];
    const float* ff_wdown = (const float*)d_in[16];
    float* out = (float*)d_out;

    float *x1, *x2;
    __nv_bfloat16 *norm_bf, *normc_bf, *qkv_bf, *lin2_bf, *q_bf, *k_bf, *v_bf, *ao_bf, *ag_bf;
    __nv_bfloat16 *wqkv_bf, *wout1_bf, *wq_bf, *wkv_bf, *wout2_bf, *wup_bf, *wdown_bf;
    cudaGetSymbolAddress((void**)&x1, g_x1);
    cudaGetSymbolAddress((void**)&x2, g_x2);
    cudaGetSymbolAddress((void**)&norm_bf,  g_norm_bf);
    cudaGetSymbolAddress((void**)&normc_bf, g_normc_bf);
    cudaGetSymbolAddress((void**)&qkv_bf,   g_qkv_bf);
    cudaGetSymbolAddress((void**)&lin2_bf,  g_lin2_bf);
    cudaGetSymbolAddress((void**)&q_bf,     g_q_bf);
    cudaGetSymbolAddress((void**)&k_bf,     g_k_bf);
    cudaGetSymbolAddress((void**)&v_bf,     g_v_bf);
    cudaGetSymbolAddress((void**)&ao_bf,    g_ao_bf);
    cudaGetSymbolAddress((void**)&ag_bf,    g_ag_bf);
    cudaGetSymbolAddress((void**)&wqkv_bf,  g_wqkv_bf);
    cudaGetSymbolAddress((void**)&wout1_bf, g_wout1_bf);
    cudaGetSymbolAddress((void**)&wq_bf,    g_wq_bf);
    cudaGetSymbolAddress((void**)&wkv_bf,   g_wkv_bf);
    cudaGetSymbolAddress((void**)&wout2_bf, g_wout2_bf);
    cudaGetSymbolAddress((void**)&wup_bf,   g_wup_bf);
    cudaGetSymbolAddress((void**)&wdown_bf, g_wdown_bf);

    static bool init_done = false;
    static cudaStream_t s2;
    static cudaEvent_t evFork1, evJoin1, evFork2, evJoin2;
    if (!init_done) {
        cudaFuncSetAttribute((const void*)gemm_bf16<128,1>, cudaFuncAttributeMaxDynamicSharedMemorySize, GSMEM(128));
        cudaFuncSetAttribute((const void*)gemm_bf16<128,2>, cudaFuncAttributeMaxDynamicSharedMemorySize, GSMEM(128));
        cudaFuncSetAttribute((const void*)gemm_bf16<64,0>,  cudaFuncAttributeMaxDynamicSharedMemorySize, GSMEM(64));
        cudaFuncSetAttribute((const void*)gemm_bf16<64,1>,  cudaFuncAttributeMaxDynamicSharedMemorySize, GSMEM(64));
        cudaFuncSetAttribute((const void*)attn_bf, cudaFuncAttributeMaxDynamicSharedMemorySize, ATT_SMEM);
        cudaStreamCreateWithFlags(&s2, cudaStreamNonBlocking);
        cudaEventCreateWithFlags(&evFork1, cudaEventDisableTiming);
        cudaEventCreateWithFlags(&evJoin1, cudaEventDisableTiming);
        cudaEventCreateWithFlags(&evFork2, cudaEventDisableTiming);
        cudaEventCreateWithFlags(&evJoin2, cudaEventDisableTiming);
        init_done = true;
    }

    const int packBlocks = (B_ * L_ * H_ * 32 + 255) / 256;

    // ---- fork stream2: convert late-use weights while self-attn runs -------
    cudaEventRecord(evFork1, 0);
    cudaStreamWaitEvent(s2, evFork1, 0);
    {
        ConvTab t;
        t.src[0] = (const float4*)sa_wout;  t.dst[0] = (uint2*)wout1_bf; t.n4[0] = 768*768/4;
        t.src[1] = (const float4*)ca_wq;    t.dst[1] = (uint2*)wq_bf;    t.n4[1] = 768*768/4;
        t.src[2] = (const float4*)ca_wkv;   t.dst[2] = (uint2*)wkv_bf;   t.n4[2] = 1536*768/4;
        t.src[3] = (const float4*)ca_wout;  t.dst[3] = (uint2*)wout2_bf; t.n4[3] = 768*768/4;
        t.src[4] = (const float4*)ff_wdown; t.dst[4] = (uint2*)wdown_bf; t.n4[4] = 768*2304/4;
        // grid.x sized for the LARGEST table entry (ff_wdown: 442368 float4s)
        conv5_kernel<<<dim3((768*2304/4 + 255)/256, 5), 256, 0, s2>>>(t);
        convup_kernel<<<(UPN_*(D_/4) + 255)/256, 256, 0, s2>>>(ff_wup, wup_bf);
    }

    // ---- main stream: wqkv conversion + self attention ----
    conv1_kernel<<<(2304*768/4 + 255)/256, 256>>>((const float4*)sa_wqkv, (uint2*)wqkv_bf, 2304*768/4);
    rmsnorm_kernel<<<M_, 256>>>(x, sa_norm, norm_bf);
    gemm_bf16<128,1><<<dim3(2304/128, M_/128), 256, GSMEM(128)>>>(norm_bf, wqkv_bf, nullptr, nullptr, qkv_bf, M_, 2304, D_);
    qkv_pack<<<packBlocks, 256>>>(qkv_bf, 2304, 0, qkv_bf, 2304, 768, 1536,
                                  pos, pos, sa_scale, q_bf, k_bf, v_bf);
    attn_bf<<<dim3(L_/128, B_*H_), 256, ATT_SMEM>>>(q_bf, k_bf, v_bf, ao_bf);

    // ---- join: all other weights now ready ----
    cudaEventRecord(evJoin1, s2);
    cudaStreamWaitEvent(0, evJoin1, 0);

    gemm_bf16<64,0><<<dim3(D_/128, M_/64), 256, GSMEM(64)>>>(ao_bf, wout1_bf, x, x1, nullptr, M_, D_, D_);

    // ---- cross attention ----
    rmsnorm_kernel<<<M_, 256>>>(x1, ca_norm, norm_bf);
    rmsnorm_kernel<<<M_, 256>>>(x_cross, ca_normc, normc_bf);

    // fork: run ca_q GEMM on s2 concurrently with kv GEMM
    cudaEventRecord(evFork2, 0);
    cudaStreamWaitEvent(s2, evFork2, 0);
    gemm_bf16<64,1><<<dim3(D_/128, M_/64), 256, GSMEM(64), s2>>>(norm_bf, wq_bf, nullptr, nullptr, lin2_bf, M_, D_, D_);
    gemm_bf16<128,1><<<dim3(1536/128, M_/128), 256, GSMEM(128)>>>(normc_bf, wkv_bf, nullptr, nullptr, qkv_bf, M_, 1536, D_);
    cudaEventRecord(evJoin2, s2);
    cudaStreamWaitEvent(0, evJoin2, 0);

    qkv_pack<<<packBlocks, 256>>>(lin2_bf, 768, 0, qkv_bf, 1536, 0, 768,
                                  pos, pos_cross, ca_scale, q_bf, k_bf, v_bf);
    attn_bf<<<dim3(L_/128, B_*H_), 256, ATT_SMEM>>>(q_bf, k_bf, v_bf, ao_bf);
    gemm_bf16<64,0><<<dim3(D_/128, M_/64), 256, GSMEM(64)>>>(ao_bf, wout2_bf, x1, x2, nullptr, M_, D_, D_);

    // ---- feed forward (silu fused in up-GEMM epilogue) ----
    rmsnorm_kernel<<<M_, 256>>>(x2, ff_norm, norm_bf);
    gemm_bf16<128,2><<<dim3(UPN_/128, M_/128), 256, GSMEM(128)>>>(norm_bf, wup_bf, nullptr, nullptr, ag_bf, M_, UPN_, D_);
    gemm_bf16<64,0><<<dim3(D_/128, M_/64), 256, GSMEM(64)>>>(ag_bf, wdown_bf, x2, out, nullptr, M_, D_, DFF_);
}

// round 16
// speedup vs baseline: 1.1349x; 1.0425x over previous
#include <cuda_runtime.h>
#include <cuda_bf16.h>
#include <cstdint>

#define B_ 2
#define L_ 2048
#define D_ 768
#define H_ 12
#define DH_ 64
#define M_ (B_*L_)
#define DFF_ 2304
#define UPN_ (2*DFF_)

// ---------------- scratch ----------------
__device__ float g_x1 [M_*D_];
__device__ float g_x2 [M_*D_];

__device__ __nv_bfloat16 g_norm_bf [M_*D_];
__device__ __nv_bfloat16 g_normc_bf[M_*D_];
__device__ __nv_bfloat16 g_qkv_bf  [M_*2304];
__device__ __nv_bfloat16 g_lin2_bf [M_*D_];
__device__ __nv_bfloat16 g_q_bf    [B_*H_*L_*DH_];
__device__ __nv_bfloat16 g_k_bf    [B_*H_*L_*DH_];
__device__ __nv_bfloat16 g_v_bf    [B_*H_*L_*DH_];
__device__ __nv_bfloat16 g_ao_bf   [M_*D_];
__device__ __nv_bfloat16 g_ag_bf   [M_*DFF_];

__device__ __nv_bfloat16 g_wqkv_bf [2304*768];
__device__ __nv_bfloat16 g_wout1_bf[768*768];
__device__ __nv_bfloat16 g_wq_bf   [768*768];
__device__ __nv_bfloat16 g_wkv_bf  [1536*768];
__device__ __nv_bfloat16 g_wout2_bf[768*768];
__device__ __nv_bfloat16 g_wup_bf  [4608*768];   // permuted: row 2j=a_j, 2j+1=g_j
__device__ __nv_bfloat16 g_wdown_bf[768*2304];

// ---------------- mma / ldmatrix helpers ----------------
__device__ __forceinline__ void mma_bf16(float c[4], const uint32_t a[4], const uint32_t b[2]) {
    asm volatile("mma.sync.aligned.m16n8k16.row.col.f32.bf16.bf16.f32 "
                 "{%0,%1,%2,%3},{%4,%5,%6,%7},{%8,%9},{%0,%1,%2,%3};\n"
                 : "+f"(c[0]), "+f"(c[1]), "+f"(c[2]), "+f"(c[3])
                 : "r"(a[0]), "r"(a[1]), "r"(a[2]), "r"(a[3]), "r"(b[0]), "r"(b[1]));
}
__device__ __forceinline__ void ldsm_x4(uint32_t r[4], uint32_t addr) {
    asm volatile("ldmatrix.sync.aligned.m8n8.x4.shared.b16 {%0,%1,%2,%3}, [%4];"
                 : "=r"(r[0]), "=r"(r[1]), "=r"(r[2]), "=r"(r[3]) : "r"(addr));
}
__device__ __forceinline__ void ldsm_x4_t(uint32_t r[4], uint32_t addr) {
    asm volatile("ldmatrix.sync.aligned.m8n8.x4.trans.shared.b16 {%0,%1,%2,%3}, [%4];"
                 : "=r"(r[0]), "=r"(r[1]), "=r"(r[2]), "=r"(r[3]) : "r"(addr));
}
__device__ __forceinline__ uint32_t pk_bf(float a, float b) {
    __nv_bfloat162 t = __floats2bfloat162_rn(a, b);
    return *(uint32_t*)&t;
}

// ---------------- weight conversion ----------------
struct ConvTab {
    const float4* src[5];
    uint2*        dst[5];
    int           n4[5];
};
__global__ void conv5_kernel(ConvTab t) {
    int r = blockIdx.y;
    int i = blockIdx.x * 256 + threadIdx.x;
    if (i >= t.n4[r]) return;
    float4 v = t.src[r][i];
    __nv_bfloat162 lo = __floats2bfloat162_rn(v.x, v.y);
    __nv_bfloat162 hi = __floats2bfloat162_rn(v.z, v.w);
    uint2 o; o.x = *(uint32_t*)&lo; o.y = *(uint32_t*)&hi;
    t.dst[r][i] = o;
}
__global__ void conv1_kernel(const float4* __restrict__ src, uint2* __restrict__ dst, int n4) {
    int i = blockIdx.x * 256 + threadIdx.x;
    if (i >= n4) return;
    float4 v = src[i];
    __nv_bfloat162 lo = __floats2bfloat162_rn(v.x, v.y);
    __nv_bfloat162 hi = __floats2bfloat162_rn(v.z, v.w);
    uint2 o; o.x = *(uint32_t*)&lo; o.y = *(uint32_t*)&hi;
    dst[i] = o;
}
__global__ void convup_kernel(const float* __restrict__ src, __nv_bfloat16* __restrict__ dst) {
    int i = blockIdx.x * 256 + threadIdx.x;
    if (i >= UPN_ * (D_ / 4)) return;
    int p  = i / (D_ / 4);
    int kc = (i % (D_ / 4)) * 4;
    int srow = (p & 1) ? (DFF_ + (p >> 1)) : (p >> 1);
    float4 v = *(const float4*)(src + (size_t)srow * D_ + kc);
    __nv_bfloat162 lo = __floats2bfloat162_rn(v.x, v.y);
    __nv_bfloat162 hi = __floats2bfloat162_rn(v.z, v.w);
    uint2 o; o.x = *(uint32_t*)&lo; o.y = *(uint32_t*)&hi;
    *(uint2*)(dst + (size_t)p * D_ + kc) = o;
}

// ---------------- rmsnorm -> bf16: one WARP per row, no block sync ----------
__global__ void rmsnorm_kernel(const float* __restrict__ x, const float* __restrict__ sc,
                               __nv_bfloat16* __restrict__ out) {
    int row = blockIdx.x * 8 + (threadIdx.x >> 5);
    int lane = threadIdx.x & 31;
    const float4* xr = (const float4*)(x + (size_t)row * D_);
    const float4* sr = (const float4*)sc;

    float4 v[6];
    float s = 0.f;
    #pragma unroll
    for (int j = 0; j < 6; j++) {
        v[j] = xr[lane + j * 32];
        s += v[j].x * v[j].x + v[j].y * v[j].y + v[j].z * v[j].z + v[j].w * v[j].w;
    }
    #pragma unroll
    for (int o = 16; o > 0; o >>= 1) s += __shfl_xor_sync(0xffffffffu, s, o);
    float r = rsqrtf(s / (float)D_ + 1e-6f);

    uint2* orow = (uint2*)(out + (size_t)row * D_);
    #pragma unroll
    for (int j = 0; j < 6; j++) {
        float4 scv = sr[lane + j * 32];
        __nv_bfloat162 lo = __floats2bfloat162_rn(v[j].x * scv.x * r, v[j].y * scv.y * r);
        __nv_bfloat162 hi = __floats2bfloat162_rn(v[j].z * scv.z * r, v[j].w * scv.w * r);
        uint2 o; o.x = *(uint32_t*)&lo; o.y = *(uint32_t*)&hi;
        orow[lane + j * 32] = o;
    }
}

// ---------------- bf16 GEMM NT: BM x 128, BK=64, 3-stage, 1 barrier/iter ----
#define SLDH 72
#define GSMEM(BM) (3 * ((BM) + 128) * SLDH * 2)

template<int BM, int MODE>
__global__ __launch_bounds__(256, 2)
void gemm_bf16(const __nv_bfloat16* __restrict__ A,
               const __nv_bfloat16* __restrict__ Bw,
               const float* __restrict__ R,
               float* __restrict__ Cf,
               __nv_bfloat16* __restrict__ Cb,
               int M, int N, int K) {
    extern __shared__ __nv_bfloat16 smh[];
    constexpr int ATILE = BM * SLDH;
    constexpr int BTILE = 128 * SLDH;
    constexpr int MI = BM / 32;
    __nv_bfloat16* As = smh;
    __nv_bfloat16* Bs = smh + 3 * ATILE;

    const int tid = threadIdx.x;
    const int m0 = blockIdx.y * BM, n0 = blockIdx.x * 128;
    const int w = tid >> 5, lane = tid & 31;
    const int wm = w >> 2, wn = w & 3;
    const int g = lane >> 2, t4 = lane & 3;

    const int arow = (lane & 7) + ((lane >> 3) & 1) * 8;
    const int acol = (lane >> 4) * 8;
    const int brow = (lane & 7) + (lane >> 4) * 8;
    const int bcol = ((lane >> 3) & 1) * 8;

    float acc[MI][4][4];
    #pragma unroll
    for (int i = 0; i < MI; i++)
        #pragma unroll
        for (int j = 0; j < 4; j++)
            #pragma unroll
            for (int r = 0; r < 4; r++) acc[i][j][r] = 0.f;

    auto load_tiles = [&](int stage, int k0) {
        __nv_bfloat16* as = As + stage * ATILE;
        __nv_bfloat16* bs = Bs + stage * BTILE;
        #pragma unroll
        for (int i = 0; i < BM / 32; i++) {
            int id = tid + i * 256;
            int r = id >> 3, c = (id & 7) * 8;
            uint32_t sa = (uint32_t)__cvta_generic_to_shared(as + r * SLDH + c);
            const __nv_bfloat16* ga = A + (size_t)(m0 + r) * K + k0 + c;
            asm volatile("cp.async.cg.shared.global [%0], [%1], 16;\n" :: "r"(sa), "l"(ga));
        }
        #pragma unroll
        for (int i = 0; i < 4; i++) {
            int id = tid + i * 256;
            int r = id >> 3, c = (id & 7) * 8;
            uint32_t sb = (uint32_t)__cvta_generic_to_shared(bs + r * SLDH + c);
            const __nv_bfloat16* gb = Bw + (size_t)(n0 + r) * K + k0 + c;
            asm volatile("cp.async.cg.shared.global [%0], [%1], 16;\n" :: "r"(sb), "l"(gb));
        }
        asm volatile("cp.async.commit_group;\n");
    };

    const int numK = K >> 6;
    load_tiles(0, 0);
    load_tiles(1, 64);

    for (int kt = 0; kt < numK; kt++) {
        if (kt + 1 < numK) asm volatile("cp.async.wait_group 1;\n");
        else               asm volatile("cp.async.wait_group 0;\n");
        __syncthreads();
        if (kt + 2 < numK) load_tiles((kt + 2) % 3, (kt + 2) * 64);

        const __nv_bfloat16* as = As + (kt % 3) * ATILE;
        const __nv_bfloat16* bs = Bs + (kt % 3) * BTILE;

        #pragma unroll
        for (int kb = 0; kb < 4; kb++) {
            uint32_t af[MI][4], bf[4][2];
            #pragma unroll
            for (int mi = 0; mi < MI; mi++) {
                int mr = wm * (BM / 2) + mi * 16 + arow;
                uint32_t ad = (uint32_t)__cvta_generic_to_shared(as + mr * SLDH + kb * 16 + acol);
                ldsm_x4(af[mi], ad);
            }
            #pragma unroll
            for (int np = 0; np < 2; np++) {
                int nr = wn * 32 + np * 16 + brow;
                uint32_t bd = (uint32_t)__cvta_generic_to_shared(bs + nr * SLDH + kb * 16 + bcol);
                uint32_t q[4];
                ldsm_x4(q, bd);
                bf[np*2  ][0] = q[0]; bf[np*2  ][1] = q[1];
                bf[np*2+1][0] = q[2]; bf[np*2+1][1] = q[3];
            }
            #pragma unroll
            for (int mi = 0; mi < MI; mi++)
                #pragma unroll
                for (int ni = 0; ni < 4; ni++)
                    mma_bf16(acc[mi][ni], af[mi], bf[ni]);
        }
    }

    #pragma unroll
    for (int mi = 0; mi < MI; mi++) {
        int r0 = m0 + wm * (BM / 2) + mi * 16 + g;
        #pragma unroll
        for (int ni = 0; ni < 4; ni++) {
            int cc = n0 + wn * 32 + ni * 8 + 2 * t4;
            float a0 = acc[mi][ni][0], a1 = acc[mi][ni][1];
            float a2 = acc[mi][ni][2], a3 = acc[mi][ni][3];
            if (MODE == 0) {
                float2 r0v = *(const float2*)(R + (size_t)r0 * N + cc);
                float2 r1v = *(const float2*)(R + (size_t)(r0 + 8) * N + cc);
                *(float2*)(Cf + (size_t)r0 * N + cc)       = make_float2(a0 + r0v.x, a1 + r0v.y);
                *(float2*)(Cf + (size_t)(r0 + 8) * N + cc) = make_float2(a2 + r1v.x, a3 + r1v.y);
            } else if (MODE == 1) {
                *(__nv_bfloat162*)(Cb + (size_t)r0 * N + cc)       = __floats2bfloat162_rn(a0, a1);
                *(__nv_bfloat162*)(Cb + (size_t)(r0 + 8) * N + cc) = __floats2bfloat162_rn(a2, a3);
            } else {
                int jj = cc >> 1;
                float s0 = a0 * (a1 / (1.f + __expf(-a1)));
                float s1 = a2 * (a3 / (1.f + __expf(-a3)));
                Cb[(size_t)r0 * DFF_ + jj]       = __float2bfloat16(s0);
                Cb[(size_t)(r0 + 8) * DFF_ + jj] = __float2bfloat16(s1);
            }
        }
    }
}

// ---------------- fused q/k cos-scale+RoPE + v copy (one warp per item) -----
__device__ __forceinline__ float theta_of(int j, int h, float p0, float p1, float p2) {
    int i = j >> 3, f = j & 7;
    float pc = (i == 0) ? p0 : ((i == 1) ? p1 : p2);
    float freq = 3.14159265358979f * __expf((float)(f * 12 + h) * 0.02398526136f);
    return pc * freq;
}

__device__ __forceinline__ void rope_vec(float* shrow, float v0, float v1,
                                         int lane, int h, float sscale,
                                         float p0, float p1, float p2,
                                         __nv_bfloat16* dst) {
    float ss = v0 * v0 + v1 * v1;
    #pragma unroll
    for (int o = 16; o > 0; o >>= 1) ss += __shfl_xor_sync(0xffffffffu, ss, o);
    float f = sscale * rsqrtf(ss + 1e-6f);
    shrow[lane] = v0 * f; shrow[lane + 32] = v1 * f;
    __syncwarp();

    float out0, out1;
    {
        int d = lane;
        if (d < 24) {
            float th = theta_of(d, h, p0, p1, p2);
            float s, c; __sincosf(th, &s, &c);
            out0 = shrow[d] * c - shrow[d + 24] * s;
        } else {
            float th = theta_of(d - 24, h, p0, p1, p2);
            float s, c; __sincosf(th, &s, &c);
            out0 = shrow[d] * c + shrow[d - 24] * s;
        }
    }
    {
        int d = lane + 32;
        if (d < 48) {
            float th = theta_of(d - 24, h, p0, p1, p2);
            float s, c; __sincosf(th, &s, &c);
            out1 = shrow[d] * c + shrow[d - 24] * s;
        } else {
            out1 = shrow[d];
        }
    }
    __syncwarp();
    dst[lane] = __float2bfloat16(out0);
    dst[lane + 32] = __float2bfloat16(out1);
}

__global__ void qkv_pack(const __nv_bfloat16* __restrict__ srcq, int strq, int offq,
                         const __nv_bfloat16* __restrict__ srck, int strk, int offk, int offv,
                         const float* __restrict__ posq, const float* __restrict__ posk,
                         const float* __restrict__ hscale,
                         __nv_bfloat16* __restrict__ dq, __nv_bfloat16* __restrict__ dk,
                         __nv_bfloat16* __restrict__ dv) {
    int wg = (blockIdx.x * blockDim.x + threadIdx.x) >> 5;
    int lane = threadIdx.x & 31;
    if (wg >= B_ * L_ * H_) return;
    int h = wg % H_;
    int bl = wg / H_;
    int b = bl / L_, l = bl % L_;

    __shared__ float sh[8][64];
    float* shrow = sh[threadIdx.x >> 5];
    size_t hdst = ((size_t)(b * H_ + h) * L_ + l) * DH_;
    float s = sqrtf(hscale[h]);

    {
        const __nv_bfloat16* sp = srcq + (size_t)bl * strq + offq + h * DH_;
        float v0 = __bfloat162float(sp[lane]), v1 = __bfloat162float(sp[lane + 32]);
        float p0 = posq[(size_t)bl * 3 + 0], p1 = posq[(size_t)bl * 3 + 1], p2 = posq[(size_t)bl * 3 + 2];
        rope_vec(shrow, v0, v1, lane, h, s, p0, p1, p2, dq + hdst);
    }
    {
        const __nv_bfloat16* sp = srck + (size_t)bl * strk + offk + h * DH_;
        float v0 = __bfloat162float(sp[lane]), v1 = __bfloat162float(sp[lane + 32]);
        float p0 = posk[(size_t)bl * 3 + 0], p1 = posk[(size_t)bl * 3 + 1], p2 = posk[(size_t)bl * 3 + 2];
        rope_vec(shrow, v0, v1, lane, h, s, p0, p1, p2, dk + hdst);
    }
    if (lane < 8) {
        *(uint4*)(dv + hdst + lane * 8) =
            *(const uint4*)(srck + (size_t)bl * strk + offv + h * DH_ + lane * 8);
    }
}

// ---------------- bf16 flash attention, 3-stage cp.async KV pipeline ---------
#define ALD 72
#define ATT_STAGE (128 * ALD)
#define ATT_SMEM (3 * ATT_STAGE * 2)

__global__ __launch_bounds__(256, 2) void attn_bf(const __nv_bfloat16* __restrict__ Q,
                                                  const __nv_bfloat16* __restrict__ K,
                                                  const __nv_bfloat16* __restrict__ V,
                                                  __nv_bfloat16* __restrict__ O) {
    extern __shared__ __nv_bfloat16 KVs[];

    const int bh = blockIdx.y;
    const int q0 = blockIdx.x * 128;
    const int tid = threadIdx.x;
    const int w = tid >> 5, lane = tid & 31;
    const int g = lane >> 2, t4 = lane & 3;

    const int arow = (lane & 7) + ((lane >> 3) & 1) * 8;
    const int acol = (lane >> 4) * 8;
    const int brow = (lane & 7) + (lane >> 4) * 8;
    const int bcol = ((lane >> 3) & 1) * 8;
    const int vrow = (lane & 7) + ((lane >> 3) & 1) * 8;
    const int vcol = (lane >> 4) * 8;

    const __nv_bfloat16* qb = Q + ((size_t)bh * L_ + q0) * DH_;
    #pragma unroll
    for (int i = 0; i < 4; i++) {
        int idx = tid + i * 256;
        int r = idx >> 3, c = (idx & 7) * 8;
        *(uint4*)(KVs + r * ALD + c) = *(const uint4*)(qb + r * 64 + c);
    }
    __syncthreads();
    uint32_t qf[4][4];
    #pragma unroll
    for (int kb = 0; kb < 4; kb++) {
        uint32_t ad = (uint32_t)__cvta_generic_to_shared(
            KVs + (w * 16 + arow) * ALD + kb * 16 + acol);
        ldsm_x4(qf[kb], ad);
    }
    __syncthreads();

    const __nv_bfloat16* kbase = K + (size_t)bh * L_ * DH_;
    const __nv_bfloat16* vbase = V + (size_t)bh * L_ * DH_;

    auto load_kv = [&](int stage, int kt) {
        __nv_bfloat16* Ks = KVs + stage * ATT_STAGE;
        __nv_bfloat16* Vs = Ks + 64 * ALD;
        #pragma unroll
        for (int i = 0; i < 2; i++) {
            int idx = tid + i * 256;
            int r = idx >> 3, c = (idx & 7) * 8;
            uint32_t sk = (uint32_t)__cvta_generic_to_shared(Ks + r * ALD + c);
            asm volatile("cp.async.cg.shared.global [%0], [%1], 16;\n"
                         :: "r"(sk), "l"(kbase + (size_t)(kt + r) * 64 + c));
            uint32_t sv = (uint32_t)__cvta_generic_to_shared(Vs + r * ALD + c);
            asm volatile("cp.async.cg.shared.global [%0], [%1], 16;\n"
                         :: "r"(sv), "l"(vbase + (size_t)(kt + r) * 64 + c));
        }
        asm volatile("cp.async.commit_group;\n");
    };

    float ob[8][4];
    #pragma unroll
    for (int n = 0; n < 8; n++)
        #pragma unroll
        for (int r = 0; r < 4; r++) ob[n][r] = 0.f;
    float m0 = -1e30f, m1 = -1e30f, l0 = 0.f, l1 = 0.f;

    const int nt = L_ / 64;
    load_kv(0, 0);
    load_kv(1, 64);

    for (int t = 0; t < nt; t++) {
        if (t + 1 < nt) asm volatile("cp.async.wait_group 1;\n");
        else            asm volatile("cp.async.wait_group 0;\n");
        __syncthreads();
        if (t + 2 < nt) load_kv((t + 2) % 3, (t + 2) * 64);

        const __nv_bfloat16* Ks = KVs + (t % 3) * ATT_STAGE;
        const __nv_bfloat16* Vs = Ks + 64 * ALD;

        float sc[8][4];
        #pragma unroll
        for (int n = 0; n < 8; n++)
            #pragma unroll
            for (int r = 0; r < 4; r++) sc[n][r] = 0.f;
        #pragma unroll
        for (int kb = 0; kb < 4; kb++) {
            uint32_t bf[8][2];
            #pragma unroll
            for (int np = 0; np < 4; np++) {
                uint32_t bd = (uint32_t)__cvta_generic_to_shared(
                    Ks + (np * 16 + brow) * ALD + kb * 16 + bcol);
                uint32_t q[4];
                ldsm_x4(q, bd);
                bf[np*2  ][0] = q[0]; bf[np*2  ][1] = q[1];
                bf[np*2+1][0] = q[2]; bf[np*2+1][1] = q[3];
            }
            #pragma unroll
            for (int n = 0; n < 8; n++)
                mma_bf16(sc[n], qf[kb], bf[n]);
        }

        float rm0 = -1e30f, rm1 = -1e30f;
        #pragma unroll
        for (int n = 0; n < 8; n++) {
            rm0 = fmaxf(rm0, fmaxf(sc[n][0], sc[n][1]));
            rm1 = fmaxf(rm1, fmaxf(sc[n][2], sc[n][3]));
        }
        rm0 = fmaxf(rm0, __shfl_xor_sync(0xffffffffu, rm0, 1));
        rm0 = fmaxf(rm0, __shfl_xor_sync(0xffffffffu, rm0, 2));
        rm1 = fmaxf(rm1, __shfl_xor_sync(0xffffffffu, rm1, 1));
        rm1 = fmaxf(rm1, __shfl_xor_sync(0xffffffffu, rm1, 2));
        float nm0 = fmaxf(m0, rm0), nm1 = fmaxf(m1, rm1);
        float c0 = __expf(m0 - nm0), c1 = __expf(m1 - nm1);
        m0 = nm0; m1 = nm1;

        float ps0 = 0.f, ps1 = 0.f;
        #pragma unroll
        for (int n = 0; n < 8; n++) {
            sc[n][0] = __expf(sc[n][0] - nm0);
            sc[n][1] = __expf(sc[n][1] - nm0);
            sc[n][2] = __expf(sc[n][2] - nm1);
            sc[n][3] = __expf(sc[n][3] - nm1);
            ps0 += sc[n][0] + sc[n][1];
            ps1 += sc[n][2] + sc[n][3];
        }
        l0 = l0 * c0 + ps0;
        l1 = l1 * c1 + ps1;
        #pragma unroll
        for (int n = 0; n < 8; n++) {
            ob[n][0] *= c0; ob[n][1] *= c0;
            ob[n][2] *= c1; ob[n][3] *= c1;
        }

        uint32_t pf[4][4];
        #pragma unroll
        for (int kb = 0; kb < 4; kb++) {
            pf[kb][0] = pk_bf(sc[2*kb  ][0], sc[2*kb  ][1]);
            pf[kb][1] = pk_bf(sc[2*kb  ][2], sc[2*kb  ][3]);
            pf[kb][2] = pk_bf(sc[2*kb+1][0], sc[2*kb+1][1]);
            pf[kb][3] = pk_bf(sc[2*kb+1][2], sc[2*kb+1][3]);
        }

        #pragma unroll
        for (int kb = 0; kb < 4; kb++) {
            #pragma unroll
            for (int np = 0; np < 4; np++) {
                uint32_t vd = (uint32_t)__cvta_generic_to_shared(
                    Vs + (kb * 16 + vrow) * ALD + np * 16 + vcol);
                uint32_t q[4];
                ldsm_x4_t(q, vd);
                uint32_t vb0[2] = {q[0], q[1]};
                uint32_t vb1[2] = {q[2], q[3]};
                mma_bf16(ob[np*2  ], pf[kb], vb0);
                mma_bf16(ob[np*2+1], pf[kb], vb1);
            }
        }
    }

    l0 += __shfl_xor_sync(0xffffffffu, l0, 1);
    l0 += __shfl_xor_sync(0xffffffffu, l0, 2);
    l1 += __shfl_xor_sync(0xffffffffu, l1, 1);
    l1 += __shfl_xor_sync(0xffffffffu, l1, 2);
    float inv0 = 1.f / l0, inv1 = 1.f / l1;

    int b = bh / H_, h = bh % H_;
    int r0 = q0 + w * 16 + g;
    __nv_bfloat16* o0 = O + ((size_t)(b * L_ + r0)) * D_ + h * DH_;
    __nv_bfloat16* o1 = O + ((size_t)(b * L_ + r0 + 8)) * D_ + h * DH_;
    #pragma unroll
    for (int n = 0; n < 8; n++) {
        *(__nv_bfloat162*)(o0 + n * 8 + 2 * t4) = __floats2bfloat162_rn(ob[n][0] * inv0, ob[n][1] * inv0);
        *(__nv_bfloat162*)(o1 + n * 8 + 2 * t4) = __floats2bfloat162_rn(ob[n][2] * inv1, ob[n][3] * inv1);
    }
}

// ---------------- host launcher ----------------
extern "C" void kernel_launch(void* const* d_in, const int* in_sizes, int n_in,
                              void* d_out, int out_size) {
    const float* x        = (const float*)d_in[0];
    const float* pos      = (const float*)d_in[1];
    const float* x_cross  = (const float*)d_in[2];
    const float* pos_cross= (const float*)d_in[3];
    const float* sa_norm  = (const float*)d_in[4];
    const float* sa_wqkv  = (const float*)d_in[5];
    const float* sa_scale = (const float*)d_in[6];
    const float* sa_wout  = (const float*)d_in[7];
    const float* ca_norm  = (const float*)d_in[8];
    const float* ca_normc = (const float*)d_in[9];
    const float* ca_wq    = (const float*)d_in[10];
    const float* ca_wkv   = (const float*)d_in[11];
    const float* ca_scale = (const float*)d_in[12];
    const float* ca_wout  = (const float*)d_in[13];
    const float* ff_norm  = (const float*)d_in[14];
    const float* ff_wup   = (const float*)d_in[15];
    const float* ff_wdown = (const float*)d_in[16];
    float* out = (float*)d_out;

    float *x1, *x2;
    __nv_bfloat16 *norm_bf, *normc_bf, *qkv_bf, *lin2_bf, *q_bf, *k_bf, *v_bf, *ao_bf, *ag_bf;
    __nv_bfloat16 *wqkv_bf, *wout1_bf, *wq_bf, *wkv_bf, *wout2_bf, *wup_bf, *wdown_bf;
    cudaGetSymbolAddress((void**)&x1, g_x1);
    cudaGetSymbolAddress((void**)&x2, g_x2);
    cudaGetSymbolAddress((void**)&norm_bf,  g_norm_bf);
    cudaGetSymbolAddress((void**)&normc_bf, g_normc_bf);
    cudaGetSymbolAddress((void**)&qkv_bf,   g_qkv_bf);
    cudaGetSymbolAddress((void**)&lin2_bf,  g_lin2_bf);
    cudaGetSymbolAddress((void**)&q_bf,     g_q_bf);
    cudaGetSymbolAddress((void**)&k_bf,     g_k_bf);
    cudaGetSymbolAddress((void**)&v_bf,     g_v_bf);
    cudaGetSymbolAddress((void**)&ao_bf,    g_ao_bf);
    cudaGetSymbolAddress((void**)&ag_bf,    g_ag_bf);
    cudaGetSymbolAddress((void**)&wqkv_bf,  g_wqkv_bf);
    cudaGetSymbolAddress((void**)&wout1_bf, g_wout1_bf);
    cudaGetSymbolAddress((void**)&wq_bf,    g_wq_bf);
    cudaGetSymbolAddress((void**)&wkv_bf,   g_wkv_bf);
    cudaGetSymbolAddress((void**)&wout2_bf, g_wout2_bf);
    cudaGetSymbolAddress((void**)&wup_bf,   g_wup_bf);
    cudaGetSymbolAddress((void**)&wdown_bf, g_wdown_bf);

    static bool init_done = false;
    static cudaStream_t s2;
    static cudaEvent_t evFork1, evQkv, evJoin1, evFork2, evJoin2;
    if (!init_done) {
        cudaFuncSetAttribute((const void*)gemm_bf16<128,1>, cudaFuncAttributeMaxDynamicSharedMemorySize, GSMEM(128));
        cudaFuncSetAttribute((const void*)gemm_bf16<128,2>, cudaFuncAttributeMaxDynamicSharedMemorySize, GSMEM(128));
        cudaFuncSetAttribute((const void*)gemm_bf16<64,0>,  cudaFuncAttributeMaxDynamicSharedMemorySize, GSMEM(64));
        cudaFuncSetAttribute((const void*)gemm_bf16<64,1>,  cudaFuncAttributeMaxDynamicSharedMemorySize, GSMEM(64));
        cudaFuncSetAttribute((const void*)attn_bf, cudaFuncAttributeMaxDynamicSharedMemorySize, ATT_SMEM);
        cudaStreamCreateWithFlags(&s2, cudaStreamNonBlocking);
        cudaEventCreateWithFlags(&evFork1, cudaEventDisableTiming);
        cudaEventCreateWithFlags(&evQkv,   cudaEventDisableTiming);
        cudaEventCreateWithFlags(&evJoin1, cudaEventDisableTiming);
        cudaEventCreateWithFlags(&evFork2, cudaEventDisableTiming);
        cudaEventCreateWithFlags(&evJoin2, cudaEventDisableTiming);
        init_done = true;
    }

    const int packBlocks = (B_ * L_ * H_ * 32 + 255) / 256;

    // ---- fork stream2: wqkv first (needed soon), then late-use weights -----
    cudaEventRecord(evFork1, 0);
    cudaStreamWaitEvent(s2, evFork1, 0);
    conv1_kernel<<<(2304*768/4 + 255)/256, 256, 0, s2>>>((const float4*)sa_wqkv, (uint2*)wqkv_bf, 2304*768/4);
    cudaEventRecord(evQkv, s2);
    {
        ConvTab t;
        t.src[0] = (const float4*)sa_wout;  t.dst[0] = (uint2*)wout1_bf; t.n4[0] = 768*768/4;
        t.src[1] = (const float4*)ca_wq;    t.dst[1] = (uint2*)wq_bf;    t.n4[1] = 768*768/4;
        t.src[2] = (const float4*)ca_wkv;   t.dst[2] = (uint2*)wkv_bf;   t.n4[2] = 1536*768/4;
        t.src[3] = (const float4*)ca_wout;  t.dst[3] = (uint2*)wout2_bf; t.n4[3] = 768*768/4;
        t.src[4] = (const float4*)ff_wdown; t.dst[4] = (uint2*)wdown_bf; t.n4[4] = 768*2304/4;
        conv5_kernel<<<dim3((768*2304/4 + 255)/256, 5), 256, 0, s2>>>(t);
        convup_kernel<<<(UPN_*(D_/4) + 255)/256, 256, 0, s2>>>(ff_wup, wup_bf);
    }

    // ---- main stream: rmsnorm runs concurrently with wqkv conversion ----
    rmsnorm_kernel<<<M_/8, 256>>>(x, sa_norm, norm_bf);
    cudaStreamWaitEvent(0, evQkv, 0);
    gemm_bf16<128,1><<<dim3(2304/128, M_/128), 256, GSMEM(128)>>>(norm_bf, wqkv_bf, nullptr, nullptr, qkv_bf, M_, 2304, D_);
    qkv_pack<<<packBlocks, 256>>>(qkv_bf, 2304, 0, qkv_bf, 2304, 768, 1536,
                                  pos, pos, sa_scale, q_bf, k_bf, v_bf);
    attn_bf<<<dim3(L_/128, B_*H_), 256, ATT_SMEM>>>(q_bf, k_bf, v_bf, ao_bf);

    // ---- join: all other weights now ready ----
    cudaEventRecord(evJoin1, s2);
    cudaStreamWaitEvent(0, evJoin1, 0);

    gemm_bf16<64,0><<<dim3(D_/128, M_/64), 256, GSMEM(64)>>>(ao_bf, wout1_bf, x, x1, nullptr, M_, D_, D_);

    // ---- cross attention ----
    rmsnorm_kernel<<<M_/8, 256>>>(x1, ca_norm, norm_bf);
    rmsnorm_kernel<<<M_/8, 256>>>(x_cross, ca_normc, normc_bf);

    // fork: run ca_q GEMM on s2 concurrently with kv GEMM
    cudaEventRecord(evFork2, 0);
    cudaStreamWaitEvent(s2, evFork2, 0);
    gemm_bf16<64,1><<<dim3(D_/128, M_/64), 256, GSMEM(64), s2>>>(norm_bf, wq_bf, nullptr, nullptr, lin2_bf, M_, D_, D_);
    gemm_bf16<128,1><<<dim3(1536/128, M_/128), 256, GSMEM(128)>>>(normc_bf, wkv_bf, nullptr, nullptr, qkv_bf, M_, 1536, D_);
    cudaEventRecord(evJoin2, s2);
    cudaStreamWaitEvent(0, evJoin2, 0);

    qkv_pack<<<packBlocks, 256>>>(lin2_bf, 768, 0, qkv_bf, 1536, 0, 768,
                                  pos, pos_cross, ca_scale, q_bf, k_bf, v_bf);
    attn_bf<<<dim3(L_/128, B_*H_), 256, ATT_SMEM>>>(q_bf, k_bf, v_bf, ao_bf);
    gemm_bf16<64,0><<<dim3(D_/128, M_/64), 256, GSMEM(64)>>>(ao_bf, wout2_bf, x1, x2, nullptr, M_, D_, D_);

    // ---- feed forward (silu fused in up-GEMM epilogue) ----
    rmsnorm_kernel<<<M_/8, 256>>>(x2, ff_norm, norm_bf);
    gemm_bf16<128,2><<<dim3(UPN_/128, M_/128), 256, GSMEM(128)>>>(norm_bf, wup_bf, nullptr, nullptr, ag_bf, M_, UPN_, D_);
    gemm_bf16<64,0><<<dim3(D_/128, M_/64), 256, GSMEM(64)>>>(ag_bf, wdown_bf, x2, out, nullptr, M_, D_, DFF_);
}

// round 17
// speedup vs baseline: 1.1428x; 1.0070x over previous
#include <cuda_runtime.h>
#include <cuda_bf16.h>
#include <cstdint>

#define B_ 2
#define L_ 2048
#define D_ 768
#define H_ 12
#define DH_ 64
#define M_ (B_*L_)
#define DFF_ 2304
#define UPN_ (2*DFF_)

// ---------------- scratch ----------------
__device__ float g_x1 [M_*D_];
__device__ float g_x2 [M_*D_];

__device__ __nv_bfloat16 g_norm_bf [M_*D_];
__device__ __nv_bfloat16 g_normc_bf[M_*D_];
__device__ __nv_bfloat16 g_qkv_bf  [M_*2304];
__device__ __nv_bfloat16 g_lin2_bf [M_*D_];
__device__ __nv_bfloat16 g_q_bf    [B_*H_*L_*DH_];
__device__ __nv_bfloat16 g_k_bf    [B_*H_*L_*DH_];
__device__ __nv_bfloat16 g_ao_bf   [M_*D_];
__device__ __nv_bfloat16 g_ag_bf   [M_*DFF_];

__device__ __nv_bfloat16 g_wqkv_bf [2304*768];
__device__ __nv_bfloat16 g_wout1_bf[768*768];
__device__ __nv_bfloat16 g_wq_bf   [768*768];
__device__ __nv_bfloat16 g_wkv_bf  [1536*768];
__device__ __nv_bfloat16 g_wout2_bf[768*768];
__device__ __nv_bfloat16 g_wup_bf  [4608*768];   // permuted: row 2j=a_j, 2j+1=g_j
__device__ __nv_bfloat16 g_wdown_bf[768*2304];

// ---------------- mma / ldmatrix helpers ----------------
__device__ __forceinline__ void mma_bf16(float c[4], const uint32_t a[4], const uint32_t b[2]) {
    asm volatile("mma.sync.aligned.m16n8k16.row.col.f32.bf16.bf16.f32 "
                 "{%0,%1,%2,%3},{%4,%5,%6,%7},{%8,%9},{%0,%1,%2,%3};\n"
                 : "+f"(c[0]), "+f"(c[1]), "+f"(c[2]), "+f"(c[3])
                 : "r"(a[0]), "r"(a[1]), "r"(a[2]), "r"(a[3]), "r"(b[0]), "r"(b[1]));
}
__device__ __forceinline__ void ldsm_x4(uint32_t r[4], uint32_t addr) {
    asm volatile("ldmatrix.sync.aligned.m8n8.x4.shared.b16 {%0,%1,%2,%3}, [%4];"
                 : "=r"(r[0]), "=r"(r[1]), "=r"(r[2]), "=r"(r[3]) : "r"(addr));
}
__device__ __forceinline__ void ldsm_x4_t(uint32_t r[4], uint32_t addr) {
    asm volatile("ldmatrix.sync.aligned.m8n8.x4.trans.shared.b16 {%0,%1,%2,%3}, [%4];"
                 : "=r"(r[0]), "=r"(r[1]), "=r"(r[2]), "=r"(r[3]) : "r"(addr));
}
__device__ __forceinline__ uint32_t pk_bf(float a, float b) {
    __nv_bfloat162 t = __floats2bfloat162_rn(a, b);
    return *(uint32_t*)&t;
}

// ---------------- weight conversion ----------------
struct ConvTab {
    const float4* src[5];
    uint2*        dst[5];
    int           n4[5];
};
__global__ void conv5_kernel(ConvTab t) {
    int r = blockIdx.y;
    int i = blockIdx.x * 256 + threadIdx.x;
    if (i >= t.n4[r]) return;
    float4 v = t.src[r][i];
    __nv_bfloat162 lo = __floats2bfloat162_rn(v.x, v.y);
    __nv_bfloat162 hi = __floats2bfloat162_rn(v.z, v.w);
    uint2 o; o.x = *(uint32_t*)&lo; o.y = *(uint32_t*)&hi;
    t.dst[r][i] = o;
}
__global__ void conv1_kernel(const float4* __restrict__ src, uint2* __restrict__ dst, int n4) {
    int i = blockIdx.x * 256 + threadIdx.x;
    if (i >= n4) return;
    float4 v = src[i];
    __nv_bfloat162 lo = __floats2bfloat162_rn(v.x, v.y);
    __nv_bfloat162 hi = __floats2bfloat162_rn(v.z, v.w);
    uint2 o; o.x = *(uint32_t*)&lo; o.y = *(uint32_t*)&hi;
    dst[i] = o;
}
__global__ void convup_kernel(const float* __restrict__ src, __nv_bfloat16* __restrict__ dst) {
    int i = blockIdx.x * 256 + threadIdx.x;
    if (i >= UPN_ * (D_ / 4)) return;
    int p  = i / (D_ / 4);
    int kc = (i % (D_ / 4)) * 4;
    int srow = (p & 1) ? (DFF_ + (p >> 1)) : (p >> 1);
    float4 v = *(const float4*)(src + (size_t)srow * D_ + kc);
    __nv_bfloat162 lo = __floats2bfloat162_rn(v.x, v.y);
    __nv_bfloat162 hi = __floats2bfloat162_rn(v.z, v.w);
    uint2 o; o.x = *(uint32_t*)&lo; o.y = *(uint32_t*)&hi;
    *(uint2*)(dst + (size_t)p * D_ + kc) = o;
}

// ---------------- rmsnorm -> bf16: one WARP per row ----------
__device__ __forceinline__ void rms_row_warp(const float* __restrict__ xrow,
                                             const float* __restrict__ sc,
                                             __nv_bfloat16* __restrict__ orow_,
                                             int lane) {
    const float4* xr = (const float4*)xrow;
    const float4* sr = (const float4*)sc;
    float4 v[6];
    float s = 0.f;
    #pragma unroll
    for (int j = 0; j < 6; j++) {
        v[j] = xr[lane + j * 32];
        s += v[j].x * v[j].x + v[j].y * v[j].y + v[j].z * v[j].z + v[j].w * v[j].w;
    }
    #pragma unroll
    for (int o = 16; o > 0; o >>= 1) s += __shfl_xor_sync(0xffffffffu, s, o);
    float r = rsqrtf(s / (float)D_ + 1e-6f);
    uint2* orow = (uint2*)orow_;
    #pragma unroll
    for (int j = 0; j < 6; j++) {
        float4 scv = sr[lane + j * 32];
        __nv_bfloat162 lo = __floats2bfloat162_rn(v[j].x * scv.x * r, v[j].y * scv.y * r);
        __nv_bfloat162 hi = __floats2bfloat162_rn(v[j].z * scv.z * r, v[j].w * scv.w * r);
        uint2 o; o.x = *(uint32_t*)&lo; o.y = *(uint32_t*)&hi;
        orow[lane + j * 32] = o;
    }
}
__global__ void rmsnorm_kernel(const float* __restrict__ x, const float* __restrict__ sc,
                               __nv_bfloat16* __restrict__ out) {
    int row = blockIdx.x * 8 + (threadIdx.x >> 5);
    rms_row_warp(x + (size_t)row * D_, sc, out + (size_t)row * D_, threadIdx.x & 31);
}
// dual: rows [0,M_) from (xa,sa)->oa ; rows [M_,2M_) from (xb,sb)->ob. Uniform per block.
__global__ void rmsnorm_dual_kernel(const float* __restrict__ xa, const float* __restrict__ sa,
                                    __nv_bfloat16* __restrict__ oa,
                                    const float* __restrict__ xb, const float* __restrict__ sb,
                                    __nv_bfloat16* __restrict__ ob) {
    int row = blockIdx.x * 8 + (threadIdx.x >> 5);
    int lane = threadIdx.x & 31;
    if (row < M_) rms_row_warp(xa + (size_t)row * D_, sa, oa + (size_t)row * D_, lane);
    else {
        int r2 = row - M_;
        rms_row_warp(xb + (size_t)r2 * D_, sb, ob + (size_t)r2 * D_, lane);
    }
}

// ---------------- bf16 GEMM NT: BM x 128, BK=64, 3-stage, 1 barrier/iter ----
#define SLDH 72
#define GSMEM(BM) (3 * ((BM) + 128) * SLDH * 2)

template<int BM, int MODE>
__global__ __launch_bounds__(256, 2)
void gemm_bf16(const __nv_bfloat16* __restrict__ A,
               const __nv_bfloat16* __restrict__ Bw,
               const float* __restrict__ R,
               float* __restrict__ Cf,
               __nv_bfloat16* __restrict__ Cb,
               int M, int N, int K) {
    extern __shared__ __nv_bfloat16 smh[];
    constexpr int ATILE = BM * SLDH;
    constexpr int BTILE = 128 * SLDH;
    constexpr int MI = BM / 32;
    __nv_bfloat16* As = smh;
    __nv_bfloat16* Bs = smh + 3 * ATILE;

    const int tid = threadIdx.x;
    const int m0 = blockIdx.y * BM, n0 = blockIdx.x * 128;
    const int w = tid >> 5, lane = tid & 31;
    const int wm = w >> 2, wn = w & 3;
    const int g = lane >> 2, t4 = lane & 3;

    const int arow = (lane & 7) + ((lane >> 3) & 1) * 8;
    const int acol = (lane >> 4) * 8;
    const int brow = (lane & 7) + (lane >> 4) * 8;
    const int bcol = ((lane >> 3) & 1) * 8;

    float acc[MI][4][4];
    #pragma unroll
    for (int i = 0; i < MI; i++)
        #pragma unroll
        for (int j = 0; j < 4; j++)
            #pragma unroll
            for (int r = 0; r < 4; r++) acc[i][j][r] = 0.f;

    auto load_tiles = [&](int stage, int k0) {
        __nv_bfloat16* as = As + stage * ATILE;
        __nv_bfloat16* bs = Bs + stage * BTILE;
        #pragma unroll
        for (int i = 0; i < BM / 32; i++) {
            int id = tid + i * 256;
            int r = id >> 3, c = (id & 7) * 8;
            uint32_t sa = (uint32_t)__cvta_generic_to_shared(as + r * SLDH + c);
            const __nv_bfloat16* ga = A + (size_t)(m0 + r) * K + k0 + c;
            asm volatile("cp.async.cg.shared.global [%0], [%1], 16;\n" :: "r"(sa), "l"(ga));
        }
        #pragma unroll
        for (int i = 0; i < 4; i++) {
            int id = tid + i * 256;
            int r = id >> 3, c = (id & 7) * 8;
            uint32_t sb = (uint32_t)__cvta_generic_to_shared(bs + r * SLDH + c);
            const __nv_bfloat16* gb = Bw + (size_t)(n0 + r) * K + k0 + c;
            asm volatile("cp.async.cg.shared.global [%0], [%1], 16;\n" :: "r"(sb), "l"(gb));
        }
        asm volatile("cp.async.commit_group;\n");
    };

    const int numK = K >> 6;
    load_tiles(0, 0);
    load_tiles(1, 64);

    for (int kt = 0; kt < numK; kt++) {
        if (kt + 1 < numK) asm volatile("cp.async.wait_group 1;\n");
        else               asm volatile("cp.async.wait_group 0;\n");
        __syncthreads();
        if (kt + 2 < numK) load_tiles((kt + 2) % 3, (kt + 2) * 64);

        const __nv_bfloat16* as = As + (kt % 3) * ATILE;
        const __nv_bfloat16* bs = Bs + (kt % 3) * BTILE;

        #pragma unroll
        for (int kb = 0; kb < 4; kb++) {
            uint32_t af[MI][4], bf[4][2];
            #pragma unroll
            for (int mi = 0; mi < MI; mi++) {
                int mr = wm * (BM / 2) + mi * 16 + arow;
                uint32_t ad = (uint32_t)__cvta_generic_to_shared(as + mr * SLDH + kb * 16 + acol);
                ldsm_x4(af[mi], ad);
            }
            #pragma unroll
            for (int np = 0; np < 2; np++) {
                int nr = wn * 32 + np * 16 + brow;
                uint32_t bd = (uint32_t)__cvta_generic_to_shared(bs + nr * SLDH + kb * 16 + bcol);
                uint32_t q[4];
                ldsm_x4(q, bd);
                bf[np*2  ][0] = q[0]; bf[np*2  ][1] = q[1];
                bf[np*2+1][0] = q[2]; bf[np*2+1][1] = q[3];
            }
            #pragma unroll
            for (int mi = 0; mi < MI; mi++)
                #pragma unroll
                for (int ni = 0; ni < 4; ni++)
                    mma_bf16(acc[mi][ni], af[mi], bf[ni]);
        }
    }

    #pragma unroll
    for (int mi = 0; mi < MI; mi++) {
        int r0 = m0 + wm * (BM / 2) + mi * 16 + g;
        #pragma unroll
        for (int ni = 0; ni < 4; ni++) {
            int cc = n0 + wn * 32 + ni * 8 + 2 * t4;
            float a0 = acc[mi][ni][0], a1 = acc[mi][ni][1];
            float a2 = acc[mi][ni][2], a3 = acc[mi][ni][3];
            if (MODE == 0) {
                float2 r0v = *(const float2*)(R + (size_t)r0 * N + cc);
                float2 r1v = *(const float2*)(R + (size_t)(r0 + 8) * N + cc);
                *(float2*)(Cf + (size_t)r0 * N + cc)       = make_float2(a0 + r0v.x, a1 + r0v.y);
                *(float2*)(Cf + (size_t)(r0 + 8) * N + cc) = make_float2(a2 + r1v.x, a3 + r1v.y);
            } else if (MODE == 1) {
                *(__nv_bfloat162*)(Cb + (size_t)r0 * N + cc)       = __floats2bfloat162_rn(a0, a1);
                *(__nv_bfloat162*)(Cb + (size_t)(r0 + 8) * N + cc) = __floats2bfloat162_rn(a2, a3);
            } else {
                int jj = cc >> 1;
                float s0 = a0 * (a1 / (1.f + __expf(-a1)));
                float s1 = a2 * (a3 / (1.f + __expf(-a3)));
                Cb[(size_t)r0 * DFF_ + jj]       = __float2bfloat16(s0);
                Cb[(size_t)(r0 + 8) * DFF_ + jj] = __float2bfloat16(s1);
            }
        }
    }
}

// ---------------- fused q/k cos-scale+RoPE (one warp per item) --------------
__device__ __forceinline__ float theta_of(int j, int h, float p0, float p1, float p2) {
    int i = j >> 3, f = j & 7;
    float pc = (i == 0) ? p0 : ((i == 1) ? p1 : p2);
    float freq = 3.14159265358979f * __expf((float)(f * 12 + h) * 0.02398526136f);
    return pc * freq;
}

__device__ __forceinline__ void rope_vec(float* shrow, float v0, float v1,
                                         int lane, int h, float sscale,
                                         float p0, float p1, float p2,
                                         __nv_bfloat16* dst) {
    float ss = v0 * v0 + v1 * v1;
    #pragma unroll
    for (int o = 16; o > 0; o >>= 1) ss += __shfl_xor_sync(0xffffffffu, ss, o);
    float f = sscale * rsqrtf(ss + 1e-6f);
    shrow[lane] = v0 * f; shrow[lane + 32] = v1 * f;
    __syncwarp();

    float out0, out1;
    {
        int d = lane;
        if (d < 24) {
            float th = theta_of(d, h, p0, p1, p2);
            float s, c; __sincosf(th, &s, &c);
            out0 = shrow[d] * c - shrow[d + 24] * s;
        } else {
            float th = theta_of(d - 24, h, p0, p1, p2);
            float s, c; __sincosf(th, &s, &c);
            out0 = shrow[d] * c + shrow[d - 24] * s;
        }
    }
    {
        int d = lane + 32;
        if (d < 48) {
            float th = theta_of(d - 24, h, p0, p1, p2);
            float s, c; __sincosf(th, &s, &c);
            out1 = shrow[d] * c + shrow[d - 24] * s;
        } else {
            out1 = shrow[d];
        }
    }
    __syncwarp();
    dst[lane] = __float2bfloat16(out0);
    dst[lane + 32] = __float2bfloat16(out1);
}

__global__ void qk_pack(const __nv_bfloat16* __restrict__ srcq, int strq, int offq,
                        const __nv_bfloat16* __restrict__ srck, int strk, int offk,
                        const float* __restrict__ posq, const float* __restrict__ posk,
                        const float* __restrict__ hscale,
                        __nv_bfloat16* __restrict__ dq, __nv_bfloat16* __restrict__ dk) {
    int wg = (blockIdx.x * blockDim.x + threadIdx.x) >> 5;
    int lane = threadIdx.x & 31;
    if (wg >= B_ * L_ * H_) return;
    int h = wg % H_;
    int bl = wg / H_;
    int b = bl / L_, l = bl % L_;

    __shared__ float sh[8][64];
    float* shrow = sh[threadIdx.x >> 5];
    size_t hdst = ((size_t)(b * H_ + h) * L_ + l) * DH_;
    float s = sqrtf(hscale[h]);

    {
        const __nv_bfloat16* sp = srcq + (size_t)bl * strq + offq + h * DH_;
        float v0 = __bfloat162float(sp[lane]), v1 = __bfloat162float(sp[lane + 32]);
        float p0 = posq[(size_t)bl * 3 + 0], p1 = posq[(size_t)bl * 3 + 1], p2 = posq[(size_t)bl * 3 + 2];
        rope_vec(shrow, v0, v1, lane, h, s, p0, p1, p2, dq + hdst);
    }
    {
        const __nv_bfloat16* sp = srck + (size_t)bl * strk + offk + h * DH_;
        float v0 = __bfloat162float(sp[lane]), v1 = __bfloat162float(sp[lane + 32]);
        float p0 = posk[(size_t)bl * 3 + 0], p1 = posk[(size_t)bl * 3 + 1], p2 = posk[(size_t)bl * 3 + 2];
        rope_vec(shrow, v0, v1, lane, h, s, p0, p1, p2, dk + hdst);
    }
}

// ---------------- bf16 flash attention, V read strided from GEMM output -----
#define ALD 72
#define ATT_STAGE (128 * ALD)
#define ATT_SMEM (3 * ATT_STAGE * 2)

__global__ __launch_bounds__(256, 2) void attn_bf(const __nv_bfloat16* __restrict__ Q,
                                                  const __nv_bfloat16* __restrict__ K,
                                                  const __nv_bfloat16* __restrict__ Vsrc,
                                                  int vstr,
                                                  __nv_bfloat16* __restrict__ O) {
    extern __shared__ __nv_bfloat16 KVs[];

    const int bh = blockIdx.y;
    const int q0 = blockIdx.x * 128;
    const int tid = threadIdx.x;
    const int w = tid >> 5, lane = tid & 31;
    const int g = lane >> 2, t4 = lane & 3;
    const int bb = bh / H_, hh = bh % H_;

    const int arow = (lane & 7) + ((lane >> 3) & 1) * 8;
    const int acol = (lane >> 4) * 8;
    const int brow = (lane & 7) + (lane >> 4) * 8;
    const int bcol = ((lane >> 3) & 1) * 8;
    const int vrow = (lane & 7) + ((lane >> 3) & 1) * 8;
    const int vcol = (lane >> 4) * 8;

    const __nv_bfloat16* qb = Q + ((size_t)bh * L_ + q0) * DH_;
    #pragma unroll
    for (int i = 0; i < 4; i++) {
        int idx = tid + i * 256;
        int r = idx >> 3, c = (idx & 7) * 8;
        *(uint4*)(KVs + r * ALD + c) = *(const uint4*)(qb + r * 64 + c);
    }
    __syncthreads();
    uint32_t qf[4][4];
    #pragma unroll
    for (int kb = 0; kb < 4; kb++) {
        uint32_t ad = (uint32_t)__cvta_generic_to_shared(
            KVs + (w * 16 + arow) * ALD + kb * 16 + acol);
        ldsm_x4(qf[kb], ad);
    }
    __syncthreads();

    const __nv_bfloat16* kbase = K + (size_t)bh * L_ * DH_;
    const __nv_bfloat16* vbase = Vsrc + hh * DH_ + (size_t)(bb * L_) * vstr;

    auto load_kv = [&](int stage, int kt) {
        __nv_bfloat16* Ks = KVs + stage * ATT_STAGE;
        __nv_bfloat16* Vs = Ks + 64 * ALD;
        #pragma unroll
        for (int i = 0; i < 2; i++) {
            int idx = tid + i * 256;
            int r = idx >> 3, c = (idx & 7) * 8;
            uint32_t sk = (uint32_t)__cvta_generic_to_shared(Ks + r * ALD + c);
            asm volatile("cp.async.cg.shared.global [%0], [%1], 16;\n"
                         :: "r"(sk), "l"(kbase + (size_t)(kt + r) * 64 + c));
            uint32_t sv = (uint32_t)__cvta_generic_to_shared(Vs + r * ALD + c);
            asm volatile("cp.async.cg.shared.global [%0], [%1], 16;\n"
                         :: "r"(sv), "l"(vbase + (size_t)(kt + r) * vstr + c));
        }
        asm volatile("cp.async.commit_group;\n");
    };

    float ob[8][4];
    #pragma unroll
    for (int n = 0; n < 8; n++)
        #pragma unroll
        for (int r = 0; r < 4; r++) ob[n][r] = 0.f;
    float m0 = -1e30f, m1 = -1e30f, l0 = 0.f, l1 = 0.f;

    const int nt = L_ / 64;
    load_kv(0, 0);
    load_kv(1, 64);

    for (int t = 0; t < nt; t++) {
        if (t + 1 < nt) asm volatile("cp.async.wait_group 1;\n");
        else            asm volatile("cp.async.wait_group 0;\n");
        __syncthreads();
        if (t + 2 < nt) load_kv((t + 2) % 3, (t + 2) * 64);

        const __nv_bfloat16* Ks = KVs + (t % 3) * ATT_STAGE;
        const __nv_bfloat16* Vs = Ks + 64 * ALD;

        float sc[8][4];
        #pragma unroll
        for (int n = 0; n < 8; n++)
            #pragma unroll
            for (int r = 0; r < 4; r++) sc[n][r] = 0.f;
        #pragma unroll
        for (int kb = 0; kb < 4; kb++) {
            uint32_t bf[8][2];
            #pragma unroll
            for (int np = 0; np < 4; np++) {
                uint32_t bd = (uint32_t)__cvta_generic_to_shared(
                    Ks + (np * 16 + brow) * ALD + kb * 16 + bcol);
                uint32_t q[4];
                ldsm_x4(q, bd);
                bf[np*2  ][0] = q[0]; bf[np*2  ][1] = q[1];
                bf[np*2+1][0] = q[2]; bf[np*2+1][1] = q[3];
            }
            #pragma unroll
            for (int n = 0; n < 8; n++)
                mma_bf16(sc[n], qf[kb], bf[n]);
        }

        float rm0 = -1e30f, rm1 = -1e30f;
        #pragma unroll
        for (int n = 0; n < 8; n++) {
            rm0 = fmaxf(rm0, fmaxf(sc[n][0], sc[n][1]));
            rm1 = fmaxf(rm1, fmaxf(sc[n][2], sc[n][3]));
        }
        rm0 = fmaxf(rm0, __shfl_xor_sync(0xffffffffu, rm0, 1));
        rm0 = fmaxf(rm0, __shfl_xor_sync(0xffffffffu, rm0, 2));
        rm1 = fmaxf(rm1, __shfl_xor_sync(0xffffffffu, rm1, 1));
        rm1 = fmaxf(rm1, __shfl_xor_sync(0xffffffffu, rm1, 2));
        float nm0 = fmaxf(m0, rm0), nm1 = fmaxf(m1, rm1);
        float c0 = __expf(m0 - nm0), c1 = __expf(m1 - nm1);
        m0 = nm0; m1 = nm1;

        float ps0 = 0.f, ps1 = 0.f;
        #pragma unroll
        for (int n = 0; n < 8; n++) {
            sc[n][0] = __expf(sc[n][0] - nm0);
            sc[n][1] = __expf(sc[n][1] - nm0);
            sc[n][2] = __expf(sc[n][2] - nm1);
            sc[n][3] = __expf(sc[n][3] - nm1);
            ps0 += sc[n][0] + sc[n][1];
            ps1 += sc[n][2] + sc[n][3];
        }
        l0 = l0 * c0 + ps0;
        l1 = l1 * c1 + ps1;
        #pragma unroll
        for (int n = 0; n < 8; n++) {
            ob[n][0] *= c0; ob[n][1] *= c0;
            ob[n][2] *= c1; ob[n][3] *= c1;
        }

        uint32_t pf[4][4];
        #pragma unroll
        for (int kb = 0; kb < 4; kb++) {
            pf[kb][0] = pk_bf(sc[2*kb  ][0], sc[2*kb  ][1]);
            pf[kb][1] = pk_bf(sc[2*kb  ][2], sc[2*kb  ][3]);
            pf[kb][2] = pk_bf(sc[2*kb+1][0], sc[2*kb+1][1]);
            pf[kb][3] = pk_bf(sc[2*kb+1][2], sc[2*kb+1][3]);
        }

        #pragma unroll
        for (int kb = 0; kb < 4; kb++) {
            #pragma unroll
            for (int np = 0; np < 4; np++) {
                uint32_t vd = (uint32_t)__cvta_generic_to_shared(
                    Vs + (kb * 16 + vrow) * ALD + np * 16 + vcol);
                uint32_t q[4];
                ldsm_x4_t(q, vd);
                uint32_t vb0[2] = {q[0], q[1]};
                uint32_t vb1[2] = {q[2], q[3]};
                mma_bf16(ob[np*2  ], pf[kb], vb0);
                mma_bf16(ob[np*2+1], pf[kb], vb1);
            }
        }
    }

    l0 += __shfl_xor_sync(0xffffffffu, l0, 1);
    l0 += __shfl_xor_sync(0xffffffffu, l0, 2);
    l1 += __shfl_xor_sync(0xffffffffu, l1, 1);
    l1 += __shfl_xor_sync(0xffffffffu, l1, 2);
    float inv0 = 1.f / l0, inv1 = 1.f / l1;

    int r0 = q0 + w * 16 + g;
    __nv_bfloat16* o0 = O + ((size_t)(bb * L_ + r0)) * D_ + hh * DH_;
    __nv_bfloat16* o1 = O + ((size_t)(bb * L_ + r0 + 8)) * D_ + hh * DH_;
    #pragma unroll
    for (int n = 0; n < 8; n++) {
        *(__nv_bfloat162*)(o0 + n * 8 + 2 * t4) = __floats2bfloat162_rn(ob[n][0] * inv0, ob[n][1] * inv0);
        *(__nv_bfloat162*)(o1 + n * 8 + 2 * t4) = __floats2bfloat162_rn(ob[n][2] * inv1, ob[n][3] * inv1);
    }
}

// ---------------- host launcher ----------------
extern "C" void kernel_launch(void* const* d_in, const int* in_sizes, int n_in,
                              void* d_out, int out_size) {
    const float* x        = (const float*)d_in[0];
    const float* pos      = (const float*)d_in[1];
    const float* x_cross  = (const float*)d_in[2];
    const float* pos_cross= (const float*)d_in[3];
    const float* sa_norm  = (const float*)d_in[4];
    const float* sa_wqkv  = (const float*)d_in[5];
    const float* sa_scale = (const float*)d_in[6];
    const float* sa_wout  = (const float*)d_in[7];
    const float* ca_norm  = (const float*)d_in[8];
    const float* ca_normc = (const float*)d_in[9];
    const float* ca_wq    = (const float*)d_in[10];
    const float* ca_wkv   = (const float*)d_in[11];
    const float* ca_scale = (const float*)d_in[12];
    const float* ca_wout  = (const float*)d_in[13];
    const float* ff_norm  = (const float*)d_in[14];
    const float* ff_wup   = (const float*)d_in[15];
    const float* ff_wdown = (const float*)d_in[16];
    float* out = (float*)d_out;

    float *x1, *x2;
    __nv_bfloat16 *norm_bf, *normc_bf, *qkv_bf, *lin2_bf, *q_bf, *k_bf, *ao_bf, *ag_bf;
    __nv_bfloat16 *wqkv_bf, *wout1_bf, *wq_bf, *wkv_bf, *wout2_bf, *wup_bf, *wdown_bf;
    cudaGetSymbolAddress((void**)&x1, g_x1);
    cudaGetSymbolAddress((void**)&x2, g_x2);
    cudaGetSymbolAddress((void**)&norm_bf,  g_norm_bf);
    cudaGetSymbolAddress((void**)&normc_bf, g_normc_bf);
    cudaGetSymbolAddress((void**)&qkv_bf,   g_qkv_bf);
    cudaGetSymbolAddress((void**)&lin2_bf,  g_lin2_bf);
    cudaGetSymbolAddress((void**)&q_bf,     g_q_bf);
    cudaGetSymbolAddress((void**)&k_bf,     g_k_bf);
    cudaGetSymbolAddress((void**)&ao_bf,    g_ao_bf);
    cudaGetSymbolAddress((void**)&ag_bf,    g_ag_bf);
    cudaGetSymbolAddress((void**)&wqkv_bf,  g_wqkv_bf);
    cudaGetSymbolAddress((void**)&wout1_bf, g_wout1_bf);
    cudaGetSymbolAddress((void**)&wq_bf,    g_wq_bf);
    cudaGetSymbolAddress((void**)&wkv_bf,   g_wkv_bf);
    cudaGetSymbolAddress((void**)&wout2_bf, g_wout2_bf);
    cudaGetSymbolAddress((void**)&wup_bf,   g_wup_bf);
    cudaGetSymbolAddress((void**)&wdown_bf, g_wdown_bf);

    static bool init_done = false;
    static cudaStream_t s2;
    static cudaEvent_t evFork1, evQkv, evJoin1, evFork2, evJoin2;
    if (!init_done) {
        cudaFuncSetAttribute((const void*)gemm_bf16<128,1>, cudaFuncAttributeMaxDynamicSharedMemorySize, GSMEM(128));
        cudaFuncSetAttribute((const void*)gemm_bf16<128,2>, cudaFuncAttributeMaxDynamicSharedMemorySize, GSMEM(128));
        cudaFuncSetAttribute((const void*)gemm_bf16<64,0>,  cudaFuncAttributeMaxDynamicSharedMemorySize, GSMEM(64));
        cudaFuncSetAttribute((const void*)gemm_bf16<64,1>,  cudaFuncAttributeMaxDynamicSharedMemorySize, GSMEM(64));
        cudaFuncSetAttribute((const void*)attn_bf, cudaFuncAttributeMaxDynamicSharedMemorySize, ATT_SMEM);
        cudaStreamCreateWithFlags(&s2, cudaStreamNonBlocking);
        cudaEventCreateWithFlags(&evFork1, cudaEventDisableTiming);
        cudaEventCreateWithFlags(&evQkv,   cudaEventDisableTiming);
        cudaEventCreateWithFlags(&evJoin1, cudaEventDisableTiming);
        cudaEventCreateWithFlags(&evFork2, cudaEventDisableTiming);
        cudaEventCreateWithFlags(&evJoin2, cudaEventDisableTiming);
        init_done = true;
    }

    const int packBlocks = (B_ * L_ * H_ * 32 + 255) / 256;

    // ---- fork stream2: wqkv first (needed soon), then late-use weights -----
    cudaEventRecord(evFork1, 0);
    cudaStreamWaitEvent(s2, evFork1, 0);
    conv1_kernel<<<(2304*768/4 + 255)/256, 256, 0, s2>>>((const float4*)sa_wqkv, (uint2*)wqkv_bf, 2304*768/4);
    cudaEventRecord(evQkv, s2);
    {
        ConvTab t;
        t.src[0] = (const float4*)sa_wout;  t.dst[0] = (uint2*)wout1_bf; t.n4[0] = 768*768/4;
        t.src[1] = (const float4*)ca_wq;    t.dst[1] = (uint2*)wq_bf;    t.n4[1] = 768*768/4;
        t.src[2] = (const float4*)ca_wkv;   t.dst[2] = (uint2*)wkv_bf;   t.n4[2] = 1536*768/4;
        t.src[3] = (const float4*)ca_wout;  t.dst[3] = (uint2*)wout2_bf; t.n4[3] = 768*768/4;
        t.src[4] = (const float4*)ff_wdown; t.dst[4] = (uint2*)wdown_bf; t.n4[4] = 768*2304/4;
        conv5_kernel<<<dim3((768*2304/4 + 255)/256, 5), 256, 0, s2>>>(t);
        convup_kernel<<<(UPN_*(D_/4) + 255)/256, 256, 0, s2>>>(ff_wup, wup_bf);
    }

    // ---- main stream: rmsnorm runs concurrently with wqkv conversion ----
    rmsnorm_kernel<<<M_/8, 256>>>(x, sa_norm, norm_bf);
    cudaStreamWaitEvent(0, evQkv, 0);
    gemm_bf16<128,1><<<dim3(2304/128, M_/128), 256, GSMEM(128)>>>(norm_bf, wqkv_bf, nullptr, nullptr, qkv_bf, M_, 2304, D_);
    qk_pack<<<packBlocks, 256>>>(qkv_bf, 2304, 0, qkv_bf, 2304, 768,
                                 pos, pos, sa_scale, q_bf, k_bf);
    attn_bf<<<dim3(L_/128, B_*H_), 256, ATT_SMEM>>>(q_bf, k_bf, qkv_bf + 1536, 2304, ao_bf);

    // ---- join: all other weights now ready ----
    cudaEventRecord(evJoin1, s2);
    cudaStreamWaitEvent(0, evJoin1, 0);

    gemm_bf16<64,0><<<dim3(D_/128, M_/64), 256, GSMEM(64)>>>(ao_bf, wout1_bf, x, x1, nullptr, M_, D_, D_);

    // ---- cross attention ----
    rmsnorm_dual_kernel<<<2*(M_/8), 256>>>(x1, ca_norm, norm_bf, x_cross, ca_normc, normc_bf);

    // fork: run ca_q GEMM on s2 concurrently with kv GEMM
    cudaEventRecord(evFork2, 0);
    cudaStreamWaitEvent(s2, evFork2, 0);
    gemm_bf16<64,1><<<dim3(D_/128, M_/64), 256, GSMEM(64), s2>>>(norm_bf, wq_bf, nullptr, nullptr, lin2_bf, M_, D_, D_);
    gemm_bf16<128,1><<<dim3(1536/128, M_/128), 256, GSMEM(128)>>>(normc_bf, wkv_bf, nullptr, nullptr, qkv_bf, M_, 1536, D_);
    cudaEventRecord(evJoin2, s2);
    cudaStreamWaitEvent(0, evJoin2, 0);

    qk_pack<<<packBlocks, 256>>>(lin2_bf, 768, 0, qkv_bf, 1536, 0,
                                 pos, pos_cross, ca_scale, q_bf, k_bf);
    attn_bf<<<dim3(L_/128, B_*H_), 256, ATT_SMEM>>>(q_bf, k_bf, qkv_bf + 768, 1536, ao_bf);
    gemm_bf16<64,0><<<dim3(D_/128, M_/64), 256, GSMEM(64)>>>(ao_bf, wout2_bf, x1, x2, nullptr, M_, D_, D_);

    // ---- feed forward (silu fused in up-GEMM epilogue) ----
    rmsnorm_kernel<<<M_/8, 256>>>(x2, ff_norm, norm_bf);
    gemm_bf16<128,2><<<dim3(UPN_/128, M_/128), 256, GSMEM(128)>>>(norm_bf, wup_bf, nullptr, nullptr, ag_bf, M_, UPN_, D_);
    gemm_bf16<64,0><<<dim3(D_/128, M_/64), 256, GSMEM(64)>>>(ag_bf, wdown_bf, x2, out, nullptr, M_, D_, DFF_);
}